// round 2
// baseline (speedup 1.0000x reference)
#include <cuda_runtime.h>

// Problem constants
#define Ln   128
#define Bn   1024
#define Hd   256
#define Dd   512
#define G3   1536
#define ODEH 128
#define INU  32
#define OUTd 16
#define ROWS (Ln * Bn)  // 131072

// ---------------- scratch (device globals; no allocs allowed) ----------------
__device__ float g_X  [(size_t)ROWS * Dd];   // [L*B, 512] embeddings (u|x)   256 MB
__device__ float g_gi [(size_t)ROWS * G3];   // [L*B, 1536] input gates+b_ih  768 MB
__device__ float g_hn [(size_t)ROWS * Dd];   // hn_all[L][B][D]; hn_all[0]=0  256 MB
__device__ float g_tmp[Bn * Dd];             // per-step pre-ODE GRU output     2 MB

// ---------------- zero hn_all[0] ----------------
__global__ void k_zero() {
    g_hn[(size_t)blockIdx.x * 1024 + threadIdx.x] = 0.0f;  // 512 blocks x 1024
}

// ---------------- embeddings: X = [tanh(ext@Wu+bu), tanh(obs@Wx+bx)] ----------------
__global__ __launch_bounds__(256) void k_embed(
    const float* __restrict__ ext, const float* __restrict__ obs,
    const float* __restrict__ Wu, const float* __restrict__ bu,
    const float* __restrict__ Wx, const float* __restrict__ bx)
{
    int row0 = blockIdx.x * 4;
    __shared__ float s_e[4][INU];
    __shared__ float s_o[4][OUTd];
    int tid = threadIdx.x;
    if (tid < 4 * INU)  { int r = tid / INU,  k = tid % INU;  s_e[r][k] = ext[(size_t)(row0 + r) * (INU + 1) + k]; }
    if (tid < 4 * OUTd) { int r = tid / OUTd, k = tid % OUTd; s_o[r][k] = obs[(size_t)(row0 + r) * OUTd + k]; }
    __syncthreads();
    float bu_t = bu[tid];
    float bx_t = bx[tid];
    #pragma unroll
    for (int r = 0; r < 4; r++) {
        float au = bu_t;
        #pragma unroll
        for (int k = 0; k < INU; k++) au += s_e[r][k] * Wu[k * Hd + tid];
        float ax = bx_t;
        #pragma unroll
        for (int k = 0; k < OUTd; k++) ax += s_o[r][k] * Wx[k * Hd + tid];
        size_t base = (size_t)(row0 + r) * Dd;
        g_X[base + tid]      = tanhf(au);
        g_X[base + Hd + tid] = tanhf(ax);
    }
}

// ---------------- gi = X @ W_ih^T + b_ih  (parallel, hoisted out of scan) ----------------
// C[131072,1536] = X[131072,512] @ W[1536,512]^T ; tiles BM=128, BN=64, BK=16
#define BM1 128
#define BN1 64
#define BK1 16
__global__ __launch_bounds__(256) void k_gi(
    const float* __restrict__ W, const float* __restrict__ bih)
{
    __shared__ float a_s[BK1][BM1 + 4];  // pad: stride 132 (16B aligned, 2-way max)
    __shared__ float b_s[BK1][BN1 + 4];  // stride 68
    int row0 = blockIdx.y * BM1;
    int n0   = blockIdx.x * BN1;
    int tid  = threadIdx.x;
    int tx = tid & 15, ty = tid >> 4;

    float acc[8][4];
    #pragma unroll
    for (int i = 0; i < 8; i++)
        #pragma unroll
        for (int j = 0; j < 4; j++) acc[i][j] = 0.0f;

    for (int k0 = 0; k0 < Dd; k0 += BK1) {
        #pragma unroll
        for (int i = 0; i < 8; i++) {               // A: 128x16
            int idx = tid + i * 256;
            int r = idx >> 4, kk = idx & 15;
            a_s[kk][r] = g_X[(size_t)(row0 + r) * Dd + k0 + kk];
        }
        #pragma unroll
        for (int i = 0; i < 4; i++) {               // B: 64x16
            int idx = tid + i * 256;
            int n = idx >> 4, kk = idx & 15;
            b_s[kk][n] = W[(size_t)(n0 + n) * Dd + k0 + kk];
        }
        __syncthreads();
        #pragma unroll
        for (int kk = 0; kk < BK1; kk++) {
            float a[8], b[4];
            #pragma unroll
            for (int i = 0; i < 8; i++) a[i] = a_s[kk][ty * 8 + i];
            #pragma unroll
            for (int j = 0; j < 4; j++) b[j] = b_s[kk][tx * 4 + j];
            #pragma unroll
            for (int i = 0; i < 8; i++)
                #pragma unroll
                for (int j = 0; j < 4; j++) acc[i][j] += a[i] * b[j];
        }
        __syncthreads();
    }
    #pragma unroll
    for (int i = 0; i < 8; i++) {
        size_t rbase = (size_t)(row0 + ty * 8 + i) * G3 + n0;
        #pragma unroll
        for (int j = 0; j < 4; j++) {
            int n = tx * 4 + j;
            g_gi[rbase + n] = acc[i][j] + bih[n0 + n];
        }
    }
}

// ---------------- per-step GRU: gh = h @ W_hh^T + b_hh, fused gates ----------------
// grid (16, 8): col tile d0=32, row tile 128. 3 gates per output element.
#define BK2 16
__global__ __launch_bounds__(256) void k_gru(
    int t, const float* __restrict__ Whh, const float* __restrict__ bhh)
{
    __shared__ float a_s[BK2][128 + 4];
    __shared__ float b_s[3][BK2][32 + 4];
    const float* hprev = g_hn + (size_t)t * Bn * Dd;
    const float* gi    = g_gi + (size_t)t * Bn * G3;
    int row0 = blockIdx.y * 128;
    int d0   = blockIdx.x * 32;
    int tid  = threadIdx.x;
    int tx = tid & 15, ty = tid >> 4;

    float acc[3][8][2];
    #pragma unroll
    for (int g = 0; g < 3; g++)
        #pragma unroll
        for (int i = 0; i < 8; i++) { acc[g][i][0] = 0.0f; acc[g][i][1] = 0.0f; }

    for (int k0 = 0; k0 < Dd; k0 += BK2) {
        #pragma unroll
        for (int i = 0; i < 8; i++) {               // A: 128x16 of h_prev
            int idx = tid + i * 256;
            int r = idx >> 4, kk = idx & 15;
            a_s[kk][r] = hprev[(size_t)(row0 + r) * Dd + k0 + kk];
        }
        #pragma unroll
        for (int i = 0; i < 6; i++) {               // B: 3 gates x 32 x 16
            int idx = tid + i * 256;
            int g = idx / 512, rem = idx & 511;
            int n = rem >> 4, kk = rem & 15;
            b_s[g][kk][n] = Whh[(size_t)(g * Dd + d0 + n) * Dd + k0 + kk];
        }
        __syncthreads();
        #pragma unroll
        for (int kk = 0; kk < BK2; kk++) {
            float a[8];
            #pragma unroll
            for (int i = 0; i < 8; i++) a[i] = a_s[kk][ty * 8 + i];
            float b[3][2];
            #pragma unroll
            for (int g = 0; g < 3; g++) {
                b[g][0] = b_s[g][kk][tx * 2 + 0];
                b[g][1] = b_s[g][kk][tx * 2 + 1];
            }
            #pragma unroll
            for (int g = 0; g < 3; g++)
                #pragma unroll
                for (int i = 0; i < 8; i++) {
                    acc[g][i][0] += a[i] * b[g][0];
                    acc[g][i][1] += a[i] * b[g][1];
                }
        }
        __syncthreads();
    }
    // fused gate epilogue: r,z,n -> h_new (pre-ODE)
    #pragma unroll
    for (int i = 0; i < 8; i++) {
        int m = row0 + ty * 8 + i;
        const float* girow = gi + (size_t)m * G3;
        #pragma unroll
        for (int j = 0; j < 2; j++) {
            int d = d0 + tx * 2 + j;
            float ghr = acc[0][i][j] + bhh[d];
            float ghz = acc[1][i][j] + bhh[Dd + d];
            float ghn = acc[2][i][j] + bhh[2 * Dd + d];  // b_hh inside r* (PyTorch GRU conv.)
            float r = 1.0f / (1.0f + __expf(-(girow[d] + ghr)));
            float z = 1.0f / (1.0f + __expf(-(girow[Dd + d] + ghz)));
            float n = tanhf(girow[2 * Dd + d] + r * ghn);
            float hp = hprev[(size_t)m * Dd + d];
            g_tmp[m * Dd + d] = (1.0f - z) * n + z * hp;
        }
    }
}

// ---------------- per-step ODE MLP + Euler update; writes hn_all[t+1] ----------------
__global__ __launch_bounds__(256) void k_ode(
    int t, const float* __restrict__ W1, const float* __restrict__ b1,
    const float* __restrict__ W2, const float* __restrict__ b2,
    const float* __restrict__ ext)
{
    int b = blockIdx.x;
    int tid = threadIdx.x;
    __shared__ float s_h[Hd];
    __shared__ float s_z[ODEH];
    const float* tmp = g_tmp + (size_t)b * Dd;
    s_h[tid] = tmp[tid];
    __syncthreads();
    if (tid < ODEH) {
        float a = b1[tid];
        #pragma unroll 8
        for (int k = 0; k < Hd; k++) a += s_h[k] * W1[k * ODEH + tid];
        s_z[tid] = tanhf(a);
    }
    __syncthreads();
    float f = b2[tid];
    #pragma unroll 8
    for (int k = 0; k < ODEH; k++) f += s_z[k] * W2[k * Hd + tid];
    float dt = ext[((size_t)t * Bn + b) * (INU + 1) + INU];
    float* hnext = g_hn + (size_t)(t + 1) * Bn * Dd + (size_t)b * Dd;
    hnext[tid]      = s_h[tid] + dt * f;       // h + dt * f
    hnext[Hd + tid] = tmp[Hd + tid];           // c passthrough
}

// ---------------- output projection: y = hn_all @ WLy + bLy ----------------
__global__ __launch_bounds__(128) void k_out(
    const float* __restrict__ WLy, const float* __restrict__ bLy,
    float* __restrict__ out)
{
    __shared__ float s_w[Dd * OUTd];   // 32 KB
    __shared__ float s_h[8][Dd];       // 16 KB
    int row0 = blockIdx.x * 8;
    int tid = threadIdx.x;
    #pragma unroll
    for (int i = 0; i < 64; i++) s_w[tid + i * 128] = WLy[tid + i * 128];
    #pragma unroll
    for (int i = 0; i < 32; i++) {
        int idx = tid + i * 128;          // 0..4095
        int r = idx >> 9, k = idx & 511;
        s_h[r][k] = g_hn[(size_t)(row0 + r) * Dd + k];
    }
    __syncthreads();
    int r = tid >> 4, o = tid & 15;
    float acc = bLy[o];
    #pragma unroll 8
    for (int k = 0; k < Dd; k++) acc += s_h[r][k] * s_w[k * OUTd + o];
    out[(size_t)(row0 + r) * OUTd + o] = acc;
}

// ---------------- launch ----------------
extern "C" void kernel_launch(void* const* d_in, const int* in_sizes, int n_in,
                              void* d_out, int out_size)
{
    const float* ext = (const float*)d_in[0];
    const float* obs = (const float*)d_in[1];
    const float* Wu  = (const float*)d_in[2];
    const float* bu  = (const float*)d_in[3];
    const float* Wx  = (const float*)d_in[4];
    const float* bx  = (const float*)d_in[5];
    const float* Wih = (const float*)d_in[6];
    const float* Whh = (const float*)d_in[7];
    const float* bih = (const float*)d_in[8];
    const float* bhh = (const float*)d_in[9];
    const float* W1  = (const float*)d_in[10];
    const float* b1  = (const float*)d_in[11];
    const float* W2  = (const float*)d_in[12];
    const float* b2  = (const float*)d_in[13];
    const float* WLy = (const float*)d_in[14];
    const float* bLy = (const float*)d_in[15];
    float* out = (float*)d_out;

    k_zero<<<512, 1024>>>();                                  // hn_all[0] = 0
    k_embed<<<ROWS / 4, 256>>>(ext, obs, Wu, bu, Wx, bx);     // embeddings
    k_gi<<<dim3(G3 / BN1, ROWS / BM1), 256>>>(Wih, bih);      // hoisted input-gate GEMM

    for (int t = 0; t < Ln - 1; t++) {                        // 127 sequential steps
        k_gru<<<dim3(16, 8), 256>>>(t, Whh, bhh);
        k_ode<<<Bn, 256>>>(t, W1, b1, W2, b2, ext);
    }
    k_out<<<ROWS / 8, 128>>>(WLy, bLy, out);                  // y = hn_all @ WLy + bLy
}

// round 4
// speedup vs baseline: 1.3908x; 1.3908x over previous
#include <cuda_runtime.h>
#include <cuda_bf16.h>

// Problem constants
#define Ln   128
#define Bn   1024
#define Hd   256
#define Dd   512
#define G3   1536
#define ODEH 128
#define INU  32
#define OUTd 16
#define ROWS (Ln * Bn)  // 131072

typedef __nv_bfloat16 bf16;

// ---------------- scratch (device globals; no allocs allowed) ----------------
__device__ bf16  g_Xh [(size_t)ROWS * Dd];   // embeddings hi split
__device__ bf16  g_Xl [(size_t)ROWS * Dd];   // embeddings lo split
__device__ float g_gi [(size_t)ROWS * G3];   // input gates + b_ih (768 MB)
__device__ float g_hn [(size_t)ROWS * Dd];   // hn_all[L][B][D]; hn_all[0]=0
__device__ float g_tmp[Bn * Dd];             // per-step pre-ODE GRU output
__device__ bf16  g_hh [Bn * Dd];             // current h hi split
__device__ bf16  g_hl [Bn * Dd];             // current h lo split
__device__ bf16  g_Wih_h[G3 * Dd], g_Wih_l[G3 * Dd];
__device__ bf16  g_Whh_h[G3 * Dd], g_Whh_l[G3 * Dd];

__device__ __forceinline__ void split_bf16(float v, bf16& hi, bf16& lo) {
    hi = __float2bfloat16(v);
    lo = __float2bfloat16(v - __bfloat162float(hi));
}

// ---------------- zero hn_all[0] + h splits ----------------
__global__ void k_zero() {
    int i = blockIdx.x * 1024 + threadIdx.x;   // 512 x 1024 = 524288 = Bn*Dd
    g_hn[i] = 0.0f;
    g_hh[i] = __float2bfloat16(0.0f);
    g_hl[i] = __float2bfloat16(0.0f);
}

// ---------------- split a [3072 x 512] weight into bf16 hi/lo ----------------
__global__ void k_wsplit(const float* __restrict__ W, bf16* __restrict__ Wh, bf16* __restrict__ Wl) {
    size_t i = (size_t)blockIdx.x * 512 + threadIdx.x;
    split_bf16(W[i], Wh[i], Wl[i]);
}

// ---------------- embeddings: X = [tanh(ext@Wu+bu), tanh(obs@Wx+bx)] (bf16 split) ----------------
__global__ __launch_bounds__(256) void k_embed(
    const float* __restrict__ ext, const float* __restrict__ obs,
    const float* __restrict__ Wu, const float* __restrict__ bu,
    const float* __restrict__ Wx, const float* __restrict__ bx)
{
    int row0 = blockIdx.x * 4;
    __shared__ float s_e[4][INU];
    __shared__ float s_o[4][OUTd];
    int tid = threadIdx.x;
    if (tid < 4 * INU)  { int r = tid / INU,  k = tid % INU;  s_e[r][k] = ext[(size_t)(row0 + r) * (INU + 1) + k]; }
    if (tid < 4 * OUTd) { int r = tid / OUTd, k = tid % OUTd; s_o[r][k] = obs[(size_t)(row0 + r) * OUTd + k]; }
    __syncthreads();
    float bu_t = bu[tid];
    float bx_t = bx[tid];
    #pragma unroll
    for (int r = 0; r < 4; r++) {
        float au = bu_t;
        #pragma unroll
        for (int k = 0; k < INU; k++) au += s_e[r][k] * Wu[k * Hd + tid];
        float ax = bx_t;
        #pragma unroll
        for (int k = 0; k < OUTd; k++) ax += s_o[r][k] * Wx[k * Hd + tid];
        size_t base = (size_t)(row0 + r) * Dd;
        float vu = tanhf(au), vx = tanhf(ax);
        split_bf16(vu, g_Xh[base + tid],      g_Xl[base + tid]);
        split_bf16(vx, g_Xh[base + Hd + tid], g_Xl[base + Hd + tid]);
    }
}

// ---------------- bf16-split tensor-core GEMM: C[m, 3 gates x d] = A[m,512] @ W[3*512,512]^T ----------------
// MODE 0 (GI): epilogue = +b_ih, store to g_gi (row stride 1536)
// MODE 1 (GRU): epilogue = fused GRU gates using gi_t, bhh, hprev -> g_tmp
// Block: 256 thr (8 warps, 2x4 warp grid), tile 64(m) x 64(d) x 3 gates, BK=32.
__device__ __forceinline__ void mma16816(float* c, const unsigned* a, const unsigned* b) {
    asm volatile(
        "mma.sync.aligned.m16n8k16.row.col.f32.bf16.bf16.f32 "
        "{%0,%1,%2,%3}, {%4,%5,%6,%7}, {%8,%9}, {%0,%1,%2,%3};\n"
        : "+f"(c[0]), "+f"(c[1]), "+f"(c[2]), "+f"(c[3])
        : "r"(a[0]), "r"(a[1]), "r"(a[2]), "r"(a[3]), "r"(b[0]), "r"(b[1]));
}

#define KST 40   // smem k stride (32 + 8 pad) -> conflict-free frag loads

template<int MODE>
__global__ __launch_bounds__(256) void k_mma(
    const bf16* __restrict__ Ah, const bf16* __restrict__ Al,
    const bf16* __restrict__ Wh, const bf16* __restrict__ Wl,
    const float* __restrict__ bias,
    const float* __restrict__ gi_t, const float* __restrict__ hprev,
    float* __restrict__ outp)
{
    __shared__ __align__(16) bf16 As[2][64][KST];       // [split][m][k]
    __shared__ __align__(16) bf16 Bs[3][2][64][KST];    // [gate][split][n][k]

    const int tid = threadIdx.x;
    const int wid = tid >> 5, lane = tid & 31;
    const int warp_m = wid >> 2, warp_n = wid & 3;
    const int q = lane >> 2, tp = lane & 3;
    const int d0 = blockIdx.x * 64;
    const size_t m0 = (size_t)blockIdx.y * 64;

    float acc[3][2][2][4];
    #pragma unroll
    for (int g = 0; g < 3; g++)
        #pragma unroll
        for (int i = 0; i < 2; i++)
            #pragma unroll
            for (int j = 0; j < 2; j++)
                #pragma unroll
                for (int e = 0; e < 4; e++) acc[g][i][j][e] = 0.0f;

    const bf16* Asrc[2] = {Ah, Al};
    const bf16* Wsrc[2] = {Wh, Wl};

    for (int k0 = 0; k0 < Dd; k0 += 32) {
        // ---- load A tiles: 2 splits x 64 m x 32 k ----
        #pragma unroll
        for (int i = 0; i < 4; i++) {
            int flat = tid + i * 256;          // 0..1023 uint2 units
            int s = flat >> 9, rem = flat & 511;
            int m = rem >> 3, kq = rem & 7;
            uint2 v = *(const uint2*)(Asrc[s] + (m0 + m) * Dd + k0 + kq * 4);
            *(uint2*)&As[s][m][kq * 4] = v;
        }
        // ---- load B tiles: 3 gates x 2 splits x 64 n x 32 k ----
        #pragma unroll
        for (int i = 0; i < 12; i++) {
            int flat = tid + i * 256;          // 0..3071
            int g = flat >> 10, rem = flat & 1023;
            int s = rem >> 9, r2 = rem & 511;
            int n = r2 >> 3, kq = r2 & 7;
            uint2 v = *(const uint2*)(Wsrc[s] + (size_t)(g * Dd + d0 + n) * Dd + k0 + kq * 4);
            *(uint2*)&Bs[g][s][n][kq * 4] = v;
        }
        __syncthreads();

        #pragma unroll
        for (int ks = 0; ks < 32; ks += 16) {
            unsigned af[2][2][4];
            #pragma unroll
            for (int i2 = 0; i2 < 2; i2++)
                #pragma unroll
                for (int s = 0; s < 2; s++) {
                    int r = warp_m * 32 + i2 * 16 + q;
                    af[i2][s][0] = *(const unsigned*)&As[s][r    ][ks +     tp * 2];
                    af[i2][s][1] = *(const unsigned*)&As[s][r + 8][ks +     tp * 2];
                    af[i2][s][2] = *(const unsigned*)&As[s][r    ][ks + 8 + tp * 2];
                    af[i2][s][3] = *(const unsigned*)&As[s][r + 8][ks + 8 + tp * 2];
                }
            unsigned bfr[3][2][2][2];
            #pragma unroll
            for (int g = 0; g < 3; g++)
                #pragma unroll
                for (int s = 0; s < 2; s++)
                    #pragma unroll
                    for (int j2 = 0; j2 < 2; j2++) {
                        int n = warp_n * 16 + j2 * 8 + q;
                        bfr[g][s][j2][0] = *(const unsigned*)&Bs[g][s][n][ks +     tp * 2];
                        bfr[g][s][j2][1] = *(const unsigned*)&Bs[g][s][n][ks + 8 + tp * 2];
                    }
            #pragma unroll
            for (int g = 0; g < 3; g++)
                #pragma unroll
                for (int i2 = 0; i2 < 2; i2++)
                    #pragma unroll
                    for (int j2 = 0; j2 < 2; j2++) {
                        mma16816(acc[g][i2][j2], af[i2][0], bfr[g][0][j2]);  // ah*bh
                        mma16816(acc[g][i2][j2], af[i2][0], bfr[g][1][j2]);  // ah*bl
                        mma16816(acc[g][i2][j2], af[i2][1], bfr[g][0][j2]);  // al*bh
                    }
        }
        __syncthreads();
    }

    // ---- epilogue ----
    #pragma unroll
    for (int i2 = 0; i2 < 2; i2++)
        #pragma unroll
        for (int j2 = 0; j2 < 2; j2++)
            #pragma unroll
            for (int e = 0; e < 4; e++) {
                int m_l = warp_m * 32 + i2 * 16 + q + ((e >> 1) ? 8 : 0);
                int d_l = warp_n * 16 + j2 * 8 + tp * 2 + (e & 1);
                size_t m = m0 + m_l;
                int d = d0 + d_l;
                if (MODE == 0) {
                    size_t rb = m * G3;
                    outp[rb +            d] = acc[0][i2][j2][e] + bias[           d];
                    outp[rb + Dd       + d] = acc[1][i2][j2][e] + bias[Dd       + d];
                    outp[rb + 2 * Dd   + d] = acc[2][i2][j2][e] + bias[2 * Dd   + d];
                } else {
                    const float* gir = gi_t + m * G3;
                    float gR = acc[0][i2][j2][e] + bias[d];
                    float gZ = acc[1][i2][j2][e] + bias[Dd + d];
                    float gN = acc[2][i2][j2][e] + bias[2 * Dd + d];
                    float r = 1.0f / (1.0f + __expf(-(gir[d] + gR)));
                    float z = 1.0f / (1.0f + __expf(-(gir[Dd + d] + gZ)));
                    float nn = tanhf(gir[2 * Dd + d] + r * gN);
                    float hp = hprev[m * Dd + d];
                    outp[m * Dd + d] = (1.0f - z) * nn + z * hp;
                }
            }
}

// ---------------- per-step ODE MLP + Euler update; writes hn_all[t+1] + h splits ----------------
// 64 blocks x 16 batch rows, 256 threads.
__global__ __launch_bounds__(256) void k_ode(
    int t, const float* __restrict__ W1, const float* __restrict__ b1,
    const float* __restrict__ W2, const float* __restrict__ b2,
    const float* __restrict__ ext)
{
    __shared__ float s_h[16][Hd];    // 16 KB
    __shared__ float s_z[16][ODEH];  //  8 KB
    __shared__ float s_dt[16];
    const int m0 = blockIdx.x * 16;
    const int tid = threadIdx.x;

    // load h part (first 256 cols) of 16 rows
    #pragma unroll
    for (int i = 0; i < 16; i++) {
        int idx = tid + i * 256;          // 0..4095
        int r = idx >> 8, c = idx & 255;
        s_h[r][c] = g_tmp[(size_t)(m0 + r) * Dd + c];
    }
    if (tid < 16)
        s_dt[tid] = ext[((size_t)t * Bn + m0 + tid) * (INU + 1) + INU];
    __syncthreads();

    // phase 1: z = tanh(h @ W1 + b1) : 16 x 128 outputs, 8 rows per thread
    {
        int col = tid & 127, rg = tid >> 7;   // rg 0..1 -> rows rg*8..rg*8+7
        float a[8];
        float bb = b1[col];
        #pragma unroll
        for (int r = 0; r < 8; r++) a[r] = bb;
        for (int k = 0; k < Hd; k++) {
            float w = W1[k * ODEH + col];
            #pragma unroll
            for (int r = 0; r < 8; r++) a[r] += s_h[rg * 8 + r][k] * w;
        }
        #pragma unroll
        for (int r = 0; r < 8; r++) s_z[rg * 8 + r][col] = tanhf(a[r]);
    }
    __syncthreads();

    // phase 2: f = z @ W2 + b2 : 16 x 256 outputs, col = tid, all 16 rows
    {
        int col = tid;
        float f[16];
        float bb = b2[col];
        #pragma unroll
        for (int r = 0; r < 16; r++) f[r] = bb;
        for (int k = 0; k < ODEH; k++) {
            float w = W2[k * Hd + col];
            #pragma unroll
            for (int r = 0; r < 16; r++) f[r] += s_z[r][k] * w;
        }
        float* hnext = g_hn + (size_t)(t + 1) * Bn * Dd;
        #pragma unroll
        for (int r = 0; r < 16; r++) {
            size_t m = m0 + r;
            float hnew = s_h[r][col] + s_dt[r] * f[r];
            float cpass = g_tmp[m * Dd + Hd + col];
            size_t bi = m * Dd;
            hnext[bi + col] = hnew;
            hnext[bi + Hd + col] = cpass;
            split_bf16(hnew,  g_hh[bi + col],      g_hl[bi + col]);
            split_bf16(cpass, g_hh[bi + Hd + col], g_hl[bi + Hd + col]);
        }
    }
}

// ---------------- output projection: y = hn_all @ WLy + bLy ----------------
__global__ __launch_bounds__(128) void k_out(
    const float* __restrict__ WLy, const float* __restrict__ bLy,
    float* __restrict__ out)
{
    __shared__ float s_w[Dd * OUTd];   // 32 KB
    __shared__ float s_h[8][Dd];       // 16 KB
    int row0 = blockIdx.x * 8;
    int tid = threadIdx.x;
    #pragma unroll
    for (int i = 0; i < 64; i++) s_w[tid + i * 128] = WLy[tid + i * 128];
    #pragma unroll
    for (int i = 0; i < 32; i++) {
        int idx = tid + i * 128;          // 0..4095
        int r = idx >> 9, k = idx & 511;
        s_h[r][k] = g_hn[(size_t)(row0 + r) * Dd + k];
    }
    __syncthreads();
    int r = tid >> 4, o = tid & 15;
    float acc = bLy[o];
    #pragma unroll 8
    for (int k = 0; k < Dd; k++) acc += s_h[r][k] * s_w[k * OUTd + o];
    out[(size_t)(row0 + r) * OUTd + o] = acc;
}

// ---------------- launch ----------------
extern "C" void kernel_launch(void* const* d_in, const int* in_sizes, int n_in,
                              void* d_out, int out_size)
{
    const float* ext = (const float*)d_in[0];
    const float* obs = (const float*)d_in[1];
    const float* Wu  = (const float*)d_in[2];
    const float* bu  = (const float*)d_in[3];
    const float* Wx  = (const float*)d_in[4];
    const float* bx  = (const float*)d_in[5];
    const float* Wih = (const float*)d_in[6];
    const float* Whh = (const float*)d_in[7];
    const float* bih = (const float*)d_in[8];
    const float* bhh = (const float*)d_in[9];
    const float* W1  = (const float*)d_in[10];
    const float* b1  = (const float*)d_in[11];
    const float* W2  = (const float*)d_in[12];
    const float* b2  = (const float*)d_in[13];
    const float* WLy = (const float*)d_in[14];
    const float* bLy = (const float*)d_in[15];
    float* out = (float*)d_out;

    // resolve device-global scratch addresses
    bf16 *p_Xh, *p_Xl, *p_hh, *p_hl, *p_Wih_h, *p_Wih_l, *p_Whh_h, *p_Whh_l;
    float *p_gi, *p_hn, *p_tmp;
    cudaGetSymbolAddress((void**)&p_Xh, g_Xh);
    cudaGetSymbolAddress((void**)&p_Xl, g_Xl);
    cudaGetSymbolAddress((void**)&p_hh, g_hh);
    cudaGetSymbolAddress((void**)&p_hl, g_hl);
    cudaGetSymbolAddress((void**)&p_Wih_h, g_Wih_h);
    cudaGetSymbolAddress((void**)&p_Wih_l, g_Wih_l);
    cudaGetSymbolAddress((void**)&p_Whh_h, g_Whh_h);
    cudaGetSymbolAddress((void**)&p_Whh_l, g_Whh_l);
    cudaGetSymbolAddress((void**)&p_gi, g_gi);
    cudaGetSymbolAddress((void**)&p_hn, g_hn);
    cudaGetSymbolAddress((void**)&p_tmp, g_tmp);

    k_zero<<<512, 1024>>>();
    k_wsplit<<<G3, 512>>>(Wih, p_Wih_h, p_Wih_l);
    k_wsplit<<<G3, 512>>>(Whh, p_Whh_h, p_Whh_l);
    k_embed<<<ROWS / 4, 256>>>(ext, obs, Wu, bu, Wx, bx);

    // hoisted input-gate GEMM: gi = X @ W_ih^T + b_ih
    k_mma<0><<<dim3(Dd / 64, ROWS / 64), 256>>>(p_Xh, p_Xl, p_Wih_h, p_Wih_l,
                                                bih, nullptr, nullptr, p_gi);

    for (int t = 0; t < Ln - 1; t++) {   // 127 sequential steps
        k_mma<1><<<dim3(Dd / 64, Bn / 64), 256>>>(p_hh, p_hl, p_Whh_h, p_Whh_l,
                                                  bhh,
                                                  p_gi + (size_t)t * Bn * G3,
                                                  p_hn + (size_t)t * Bn * Dd,
                                                  p_tmp);
        k_ode<<<64, 256>>>(t, W1, b1, W2, b2, ext);
    }
    k_out<<<ROWS / 8, 128>>>(WLy, bLy, out);
}

// round 6
// speedup vs baseline: 1.9308x; 1.3883x over previous
#include <cuda_runtime.h>
#include <cuda_bf16.h>

// Problem constants
#define Ln   128
#define Bn   1024
#define Hd   256
#define Dd   512
#define G3   1536
#define ODEH 128
#define INU  32
#define OUTd 16
#define ROWS (Ln * Bn)  // 131072
#define NBLK 128        // persistent grid (<=148 SMs, 1 CTA/SM via smem)

typedef __nv_bfloat16 bf16;

// ---------------- scratch (device globals; no allocs allowed) ----------------
__device__ bf16  g_Xh [(size_t)ROWS * Dd];     // embeddings hi split (m-major)
__device__ bf16  g_Xl [(size_t)ROWS * Dd];     // embeddings lo split
__device__ float g_giT[(size_t)Ln * G3 * Bn];  // gi TRANSPOSED [t][gate*512+d][b]
__device__ float g_hnT[(size_t)Ln * Dd * Bn];  // hn history TRANSPOSED [t][d][b]
__device__ float g_tmpT[(size_t)Dd * Bn];      // GRU out TRANSPOSED [d][b]
__device__ bf16  g_hh [Bn * Dd], g_hl[Bn * Dd];  // current h splits (m-major)
__device__ bf16  g_Wih_h[G3 * Dd], g_Wih_l[G3 * Dd];
__device__ bf16  g_Whh_h[G3 * Dd], g_Whh_l[G3 * Dd];
__device__ unsigned g_bar;

// smem layout (dynamic): Ws [2][96][520] bf16 = 199680 B, then sA/[ODE overlay] 20480 B
#define WS_K 520
#define SA_K 40
#define SA_OFF 199680
#define SMEM_TOTAL (SA_OFF + 20480)

__device__ __forceinline__ void split_bf16(float v, bf16& hi, bf16& lo) {
    hi = __float2bfloat16(v);
    lo = __float2bfloat16(v - __bfloat162float(hi));
}

// ---------------- init: hn[0]=0, h splits=0, barrier=0 ----------------
__global__ void k_zero() {
    int i = blockIdx.x * 1024 + threadIdx.x;   // 512x1024 = Bn*Dd
    g_hnT[i] = 0.0f;
    g_hh[i] = __float2bfloat16(0.0f);
    g_hl[i] = __float2bfloat16(0.0f);
    if (i == 0) g_bar = 0u;
}

// ---------------- split weights into bf16 hi/lo ----------------
__global__ void k_wsplit(const float* __restrict__ W, bf16* __restrict__ Wh, bf16* __restrict__ Wl) {
    size_t i = (size_t)blockIdx.x * 512 + threadIdx.x;
    split_bf16(W[i], Wh[i], Wl[i]);
}

// ---------------- embeddings: X = [tanh(ext@Wu+bu), tanh(obs@Wx+bx)] (bf16 split) ----------------
__global__ __launch_bounds__(256) void k_embed(
    const float* __restrict__ ext, const float* __restrict__ obs,
    const float* __restrict__ Wu, const float* __restrict__ bu,
    const float* __restrict__ Wx, const float* __restrict__ bx)
{
    int row0 = blockIdx.x * 4;
    __shared__ float s_e[4][INU];
    __shared__ float s_o[4][OUTd];
    int tid = threadIdx.x;
    if (tid < 4 * INU)  { int r = tid / INU,  k = tid % INU;  s_e[r][k] = ext[(size_t)(row0 + r) * (INU + 1) + k]; }
    if (tid < 4 * OUTd) { int r = tid / OUTd, k = tid % OUTd; s_o[r][k] = obs[(size_t)(row0 + r) * OUTd + k]; }
    __syncthreads();
    float bu_t = bu[tid];
    float bx_t = bx[tid];
    #pragma unroll
    for (int r = 0; r < 4; r++) {
        float au = bu_t;
        #pragma unroll
        for (int k = 0; k < INU; k++) au += s_e[r][k] * Wu[k * Hd + tid];
        float ax = bx_t;
        #pragma unroll
        for (int k = 0; k < OUTd; k++) ax += s_o[r][k] * Wx[k * Hd + tid];
        size_t base = (size_t)(row0 + r) * Dd;
        float vu = tanhf(au), vx = tanhf(ax);
        split_bf16(vu, g_Xh[base + tid],      g_Xl[base + tid]);
        split_bf16(vx, g_Xh[base + Hd + tid], g_Xl[base + Hd + tid]);
    }
}

// ---------------- mma + grid barrier helpers ----------------
__device__ __forceinline__ void mma16816(float* c, const unsigned* a, const unsigned* b) {
    asm volatile(
        "mma.sync.aligned.m16n8k16.row.col.f32.bf16.bf16.f32 "
        "{%0,%1,%2,%3}, {%4,%5,%6,%7}, {%8,%9}, {%0,%1,%2,%3};\n"
        : "+f"(c[0]), "+f"(c[1]), "+f"(c[2]), "+f"(c[3])
        : "r"(a[0]), "r"(a[1]), "r"(a[2]), "r"(a[3]), "r"(b[0]), "r"(b[1]));
}

__device__ __forceinline__ void gbar(unsigned target) {
    __syncthreads();
    if (threadIdx.x == 0) {
        __threadfence();
        atomicAdd(&g_bar, 1u);
        while (*((volatile unsigned*)&g_bar) < target) { }
        __threadfence();
    }
    __syncthreads();
}

// load W slice (2 splits x 96 rows x 512 k) into resident smem
__device__ __forceinline__ void load_W(const bf16* __restrict__ Wh, const bf16* __restrict__ Wl,
                                       int d0, bf16* sW, int tid) {
    #pragma unroll 4
    for (int it = 0; it < 96; it++) {
        int flat = tid + it * 256;            // 0..24575 uint2 units
        int s = (flat >= 12288) ? 1 : 0;
        int rem = flat - s * 12288;
        int n = rem >> 7, kq4 = (rem & 127) << 2;
        int R = (n >> 5) * Dd + d0 + (n & 31);
        uint2 v = *(const uint2*)((s ? Wl : Wh) + (size_t)R * Dd + kq4);
        *(uint2*)(sW + ((size_t)(s * 96 + n)) * WS_K + kq4) = v;
    }
}

// GEMM over one 128-row A tile vs resident Ws (3 gates x 32 d), split-bf16 x3
__device__ __forceinline__ void gemm_tile(
    const bf16* __restrict__ Ah, const bf16* __restrict__ Al,  // row tile base, row stride Dd
    const bf16* sW, bf16* sA, float acc[3][2][2][4], int tid)
{
    const int wid = tid >> 5, lane = tid & 31;
    const int warp_m = wid >> 1, warp_n = wid & 1;
    const int q = lane >> 2, tp = lane & 3;
    const int mload = tid >> 3;   // 0..31
    const int kq4 = (tid & 7) << 2;

    #pragma unroll
    for (int g = 0; g < 3; g++)
        #pragma unroll
        for (int i2 = 0; i2 < 2; i2++)
            #pragma unroll
            for (int j2 = 0; j2 < 2; j2++)
                #pragma unroll
                for (int e = 0; e < 4; e++) acc[g][i2][j2][e] = 0.0f;

    uint2 pf[8];
    #pragma unroll
    for (int i = 0; i < 8; i++) {
        int s = i >> 2, m = (i & 3) * 32 + mload;
        pf[i] = __ldcg((const uint2*)((s ? Al : Ah) + (size_t)m * Dd + kq4));
    }
    #pragma unroll
    for (int i = 0; i < 8; i++) {
        int s = i >> 2, m = (i & 3) * 32 + mload;
        *(uint2*)(sA + (s * 128 + m) * SA_K + kq4) = pf[i];
    }
    __syncthreads();

    for (int c = 0; c < 16; c++) {
        if (c < 15) {
            #pragma unroll
            for (int i = 0; i < 8; i++) {
                int s = i >> 2, m = (i & 3) * 32 + mload;
                pf[i] = __ldcg((const uint2*)((s ? Al : Ah) + (size_t)m * Dd + (c + 1) * 32 + kq4));
            }
        }
        #pragma unroll
        for (int ks = 0; ks < 32; ks += 16) {
            unsigned af[2][2][4];
            #pragma unroll
            for (int i2 = 0; i2 < 2; i2++)
                #pragma unroll
                for (int s = 0; s < 2; s++) {
                    const bf16* base = sA + (s * 128 + warp_m * 32 + i2 * 16 + q) * SA_K + ks + tp * 2;
                    af[i2][s][0] = *(const unsigned*)(base);
                    af[i2][s][1] = *(const unsigned*)(base + 8 * SA_K);
                    af[i2][s][2] = *(const unsigned*)(base + 8);
                    af[i2][s][3] = *(const unsigned*)(base + 8 * SA_K + 8);
                }
            unsigned bfr[3][2][2][2];
            #pragma unroll
            for (int g = 0; g < 3; g++)
                #pragma unroll
                for (int s = 0; s < 2; s++)
                    #pragma unroll
                    for (int j2 = 0; j2 < 2; j2++) {
                        const bf16* bb = sW + ((size_t)(s * 96 + g * 32 + warp_n * 16 + j2 * 8 + q)) * WS_K
                                        + c * 32 + ks + tp * 2;
                        bfr[g][s][j2][0] = *(const unsigned*)(bb);
                        bfr[g][s][j2][1] = *(const unsigned*)(bb + 8);
                    }
            #pragma unroll
            for (int g = 0; g < 3; g++)
                #pragma unroll
                for (int i2 = 0; i2 < 2; i2++)
                    #pragma unroll
                    for (int j2 = 0; j2 < 2; j2++) {
                        mma16816(acc[g][i2][j2], af[i2][0], bfr[g][0][j2]);  // ah*bh
                        mma16816(acc[g][i2][j2], af[i2][0], bfr[g][1][j2]);  // ah*bl
                        mma16816(acc[g][i2][j2], af[i2][1], bfr[g][0][j2]);  // al*bh
                    }
        }
        __syncthreads();
        if (c < 15) {
            #pragma unroll
            for (int i = 0; i < 8; i++) {
                int s = i >> 2, m = (i & 3) * 32 + mload;
                *(uint2*)(sA + (s * 128 + m) * SA_K + kq4) = pf[i];
            }
            __syncthreads();
        }
    }
}

// ---------------- THE persistent kernel: gi GEMM + 127x (GRU GEMM + gates + ODE) ----------------
__global__ void __launch_bounds__(256, 1) k_persist(
    const float* __restrict__ ext,
    const float* __restrict__ bih, const float* __restrict__ bhh,
    const float* __restrict__ W1, const float* __restrict__ b1,
    const float* __restrict__ W2, const float* __restrict__ b2)
{
    extern __shared__ char smem[];
    bf16* sW = (bf16*)smem;
    bf16* sA = (bf16*)(smem + SA_OFF);
    float* s_h  = (float*)(smem + SA_OFF);           // [8][260] overlay
    float* s_z  = (float*)(smem + SA_OFF + 8320);    // [8][132]
    float* s_c  = (float*)(smem + SA_OFF + 12544);   // [8][130]
    float* s_dt = (float*)(smem + SA_OFF + 16704);   // [8]

    const int tid = threadIdx.x;
    const int bid = blockIdx.x;
    const int dtile = bid & 15, mg = bid >> 4;
    const int d0 = dtile * 32;
    const int wid = tid >> 5, lane = tid & 31;
    const int warp_m = wid >> 1, warp_n = wid & 1;
    const int q = lane >> 2, tp = lane & 3;
    const int m0ode = bid * 8;
    unsigned bar_t = 0;

    float acc[3][2][2][4];

    // preload per-thread bias values (d depends only on j2, eo)
    float bI[3][2][2], bH[3][2][2];
    #pragma unroll
    for (int g = 0; g < 3; g++)
        #pragma unroll
        for (int j2 = 0; j2 < 2; j2++)
            #pragma unroll
            for (int eo = 0; eo < 2; eo++) {
                int d = d0 + warp_n * 16 + j2 * 8 + tp * 2 + eo;
                bI[g][j2][eo] = bih[g * Dd + d];
                bH[g][j2][eo] = bhh[g * Dd + d];
            }

    // ======== Phase 1: gi = X @ W_ih^T + b_ih (127 row-tiles per block) ========
    load_W(g_Wih_h, g_Wih_l, d0, sW, tid);
    __syncthreads();
    for (int t = 0; t < 127; t++) {
        const bf16* Ah = g_Xh + ((size_t)t * Bn + mg * 128) * Dd;
        const bf16* Al = g_Xl + ((size_t)t * Bn + mg * 128) * Dd;
        gemm_tile(Ah, Al, sW, sA, acc, tid);
        float* giT = g_giT + (size_t)t * G3 * Bn;
        #pragma unroll
        for (int i2 = 0; i2 < 2; i2++)
            #pragma unroll
            for (int j2 = 0; j2 < 2; j2++)
                #pragma unroll
                for (int e = 0; e < 4; e++) {
                    int b = mg * 128 + warp_m * 32 + i2 * 16 + q + (e >> 1) * 8;
                    int d = d0 + warp_n * 16 + j2 * 8 + tp * 2 + (e & 1);
                    #pragma unroll
                    for (int g = 0; g < 3; g++)
                        giT[(size_t)(g * Dd + d) * Bn + b] = acc[g][i2][j2][e] + bI[g][j2][e & 1];
                }
    }

    // ======== Phase 2: recurrent loop ========
    load_W(g_Whh_h, g_Whh_l, d0, sW, tid);
    bar_t += NBLK; gbar(bar_t);   // gi fully written; W_hh loaded

    for (int t = 0; t < 127; t++) {
        // ---- GRU GEMM + fused gates -> g_tmpT ----
        const bf16* Ah = g_hh + (size_t)mg * 128 * Dd;
        const bf16* Al = g_hl + (size_t)mg * 128 * Dd;
        gemm_tile(Ah, Al, sW, sA, acc, tid);
        const float* giT = g_giT + (size_t)t * G3 * Bn;
        const float* hpT = g_hnT + (size_t)t * Dd * Bn;
        #pragma unroll
        for (int i2 = 0; i2 < 2; i2++)
            #pragma unroll
            for (int j2 = 0; j2 < 2; j2++)
                #pragma unroll
                for (int e = 0; e < 4; e++) {
                    int b = mg * 128 + warp_m * 32 + i2 * 16 + q + (e >> 1) * 8;
                    int d = d0 + warp_n * 16 + j2 * 8 + tp * 2 + (e & 1);
                    float gR = acc[0][i2][j2][e] + bH[0][j2][e & 1];
                    float gZ = acc[1][i2][j2][e] + bH[1][j2][e & 1];
                    float gN = acc[2][i2][j2][e] + bH[2][j2][e & 1];
                    float giR = __ldcg(&giT[(size_t)(d) * Bn + b]);
                    float giZ = __ldcg(&giT[(size_t)(Dd + d) * Bn + b]);
                    float giN = __ldcg(&giT[(size_t)(2 * Dd + d) * Bn + b]);
                    float r = 1.0f / (1.0f + __expf(-(giR + gR)));
                    float z = 1.0f / (1.0f + __expf(-(giZ + gZ)));
                    float nn = tanhf(giN + r * gN);
                    float hp = __ldcg(&hpT[(size_t)d * Bn + b]);
                    g_tmpT[(size_t)d * Bn + b] = (1.0f - z) * nn + z * hp;
                }
        bar_t += NBLK; gbar(bar_t);

        // ---- ODE MLP + Euler for rows m0ode..m0ode+7 ----
        #pragma unroll
        for (int i = 0; i < 8; i++) {                 // load h-part transposed -> s_h[r][c]
            int idx = tid + i * 256;
            int r = idx & 7, cc = idx >> 3;           // cc 0..255
            s_h[r * 260 + cc] = __ldcg(&g_tmpT[(size_t)cc * Bn + m0ode + r]);
        }
        if (tid < 8) s_dt[tid] = ext[((size_t)t * Bn + m0ode + tid) * (INU + 1) + INU];
        __syncthreads();
        {   // phase 1: z = tanh(h @ W1 + b1); 4 rows per thread
            int col = tid & 127, rg = tid >> 7;
            float a0 = b1[col], a1 = a0, a2 = a0, a3 = a0;
            #pragma unroll 4
            for (int k = 0; k < Hd; k++) {
                float w = W1[k * ODEH + col];
                a0 += s_h[(rg * 4 + 0) * 260 + k] * w;
                a1 += s_h[(rg * 4 + 1) * 260 + k] * w;
                a2 += s_h[(rg * 4 + 2) * 260 + k] * w;
                a3 += s_h[(rg * 4 + 3) * 260 + k] * w;
            }
            s_z[(rg * 4 + 0) * 132 + col] = tanhf(a0);
            s_z[(rg * 4 + 1) * 132 + col] = tanhf(a1);
            s_z[(rg * 4 + 2) * 132 + col] = tanhf(a2);
            s_z[(rg * 4 + 3) * 132 + col] = tanhf(a3);
        }
        __syncthreads();
        float hnew[8];
        {   // phase 2: f = z @ W2 + b2 ; hnew = h + dt*f ; write h splits (m-major, coalesced)
            int col = tid;
            float f[8];
            float bb = b2[col];
            #pragma unroll
            for (int r = 0; r < 8; r++) f[r] = bb;
            #pragma unroll 4
            for (int k = 0; k < ODEH; k++) {
                float w = W2[k * Hd + col];
                #pragma unroll
                for (int r = 0; r < 8; r++) f[r] += s_z[r * 132 + k] * w;
            }
            #pragma unroll
            for (int r = 0; r < 8; r++) {
                hnew[r] = s_h[r * 260 + col] + s_dt[r] * f[r];
                bf16 hi, lo; split_bf16(hnew[r], hi, lo);
                g_hh[(size_t)(m0ode + r) * Dd + col] = hi;
                g_hl[(size_t)(m0ode + r) * Dd + col] = lo;
            }
        }
        __syncthreads();
        {   int col = tid;                            // overwrite s_h with hnew
            #pragma unroll
            for (int r = 0; r < 8; r++) s_h[r * 260 + col] = hnew[r];
        }
        __syncthreads();
        float* hnT1 = g_hnT + (size_t)(t + 1) * Dd * Bn;
        #pragma unroll
        for (int i = 0; i < 8; i++) {                 // transposed write of h-part
            int idx = tid + i * 256;
            int r = idx & 7, cc = idx >> 3;
            hnT1[(size_t)cc * Bn + m0ode + r] = s_h[r * 260 + cc];
        }
        #pragma unroll
        for (int ch = 0; ch < 2; ch++) {              // c passthrough (identity in [d][b]) + splits
            int cbase = Hd + ch * 128;
            #pragma unroll
            for (int i = 0; i < 4; i++) {
                int idx = tid + i * 256;              // 8 r x 128 cl
                int r = idx & 7, cl = idx >> 3;
                float x = __ldcg(&g_tmpT[(size_t)(cbase + cl) * Bn + m0ode + r]);
                hnT1[(size_t)(cbase + cl) * Bn + m0ode + r] = x;
                s_c[r * 130 + cl] = x;
            }
            __syncthreads();
            #pragma unroll
            for (int i = 0; i < 4; i++) {
                int idx = tid + i * 256;
                int r = idx >> 7, cl = idx & 127;
                float x = s_c[r * 130 + cl];
                bf16 hi, lo; split_bf16(x, hi, lo);
                g_hh[(size_t)(m0ode + r) * Dd + cbase + cl] = hi;
                g_hl[(size_t)(m0ode + r) * Dd + cbase + cl] = lo;
            }
            __syncthreads();
        }
        bar_t += NBLK; gbar(bar_t);
    }
}

// ---------------- output projection: y[t][b][o] = sum_k hnT[t][k][b] * WLy[k][o] + bLy ----------------
__global__ __launch_bounds__(256) void k_out(
    const float* __restrict__ WLy, const float* __restrict__ bLy,
    float* __restrict__ out)
{
    __shared__ float s_w[Dd * OUTd];   // 32 KB
    int t = blockIdx.x >> 3;
    int b0 = (blockIdx.x & 7) * 128;
    int tid = threadIdx.x;
    #pragma unroll
    for (int i = 0; i < 32; i++) s_w[tid + i * 256] = WLy[tid + i * 256];
    __syncthreads();
    int b = b0 + (tid >> 1);
    int oh = (tid & 1) * 8;
    const float* hp = g_hnT + (size_t)t * Dd * Bn;
    float a[8];
    #pragma unroll
    for (int j = 0; j < 8; j++) a[j] = bLy[oh + j];
    #pragma unroll 4
    for (int k = 0; k < Dd; k++) {
        float v = __ldg(&hp[(size_t)k * Bn + b]);
        #pragma unroll
        for (int j = 0; j < 8; j++) a[j] += v * s_w[k * OUTd + oh + j];
    }
    float* op = out + ((size_t)t * Bn + b) * OUTd + oh;
    *(float4*)(op)     = make_float4(a[0], a[1], a[2], a[3]);
    *(float4*)(op + 4) = make_float4(a[4], a[5], a[6], a[7]);
}

// ---------------- launch ----------------
extern "C" void kernel_launch(void* const* d_in, const int* in_sizes, int n_in,
                              void* d_out, int out_size)
{
    const float* ext = (const float*)d_in[0];
    const float* obs = (const float*)d_in[1];
    const float* Wu  = (const float*)d_in[2];
    const float* bu  = (const float*)d_in[3];
    const float* Wx  = (const float*)d_in[4];
    const float* bx  = (const float*)d_in[5];
    const float* Wih = (const float*)d_in[6];
    const float* Whh = (const float*)d_in[7];
    const float* bih = (const float*)d_in[8];
    const float* bhh = (const float*)d_in[9];
    const float* W1  = (const float*)d_in[10];
    const float* b1  = (const float*)d_in[11];
    const float* W2  = (const float*)d_in[12];
    const float* b2  = (const float*)d_in[13];
    const float* WLy = (const float*)d_in[14];
    const float* bLy = (const float*)d_in[15];
    float* out = (float*)d_out;

    bf16 *p_Wih_h, *p_Wih_l, *p_Whh_h, *p_Whh_l;
    cudaGetSymbolAddress((void**)&p_Wih_h, g_Wih_h);
    cudaGetSymbolAddress((void**)&p_Wih_l, g_Wih_l);
    cudaGetSymbolAddress((void**)&p_Whh_h, g_Whh_h);
    cudaGetSymbolAddress((void**)&p_Whh_l, g_Whh_l);

    cudaFuncSetAttribute(k_persist, cudaFuncAttributeMaxDynamicSharedMemorySize, SMEM_TOTAL);

    k_zero<<<512, 1024>>>();
    k_wsplit<<<G3, 512>>>(Wih, p_Wih_h, p_Wih_l);
    k_wsplit<<<G3, 512>>>(Whh, p_Whh_h, p_Whh_l);
    k_embed<<<ROWS / 4, 256>>>(ext, obs, Wu, bu, Wx, bx);

    k_persist<<<NBLK, 256, SMEM_TOTAL>>>(ext, bih, bhh, W1, b1, W2, b2);

    k_out<<<Ln * 8, 256>>>(WLy, bLy, out);
}

// round 9
// speedup vs baseline: 2.1969x; 1.1378x over previous
#include <cuda_runtime.h>
#include <cuda_bf16.h>
#include <cstdint>

// Problem constants
#define Ln   128
#define Bn   1024
#define Hd   256
#define Dd   512
#define G3   1536
#define ODEH 128
#define INU  32
#define OUTd 16
#define ROWS (Ln * Bn)  // 131072
#define NBLK 128        // persistent grid, 1 CTA/SM via smem

typedef __nv_bfloat16 bf16;

// ---------------- scratch (device globals; no allocs allowed) ----------------
__device__ bf16  g_Xh [(size_t)ROWS * Dd];     // embeddings hi split (m-major)
__device__ bf16  g_Xl [(size_t)ROWS * Dd];     // embeddings lo split
__device__ float g_giT[(size_t)Ln * G3 * Bn];  // gi TRANSPOSED [t][gate*512+d][b]
__device__ float g_hnT[(size_t)Ln * Dd * Bn];  // hn history TRANSPOSED [t][d][b]
__device__ float g_tmpT[(size_t)Dd * Bn];      // GRU out TRANSPOSED [d][b]
__device__ bf16  g_hh [Bn * Dd], g_hl[Bn * Dd];  // current h splits (m-major)
__device__ bf16  g_Wih_h[G3 * Dd], g_Wih_l[G3 * Dd];
__device__ bf16  g_Whh_h[G3 * Dd], g_Whh_l[G3 * Dd];
__device__ unsigned g_bar;

// ---------------- smem map ----------------
// W: 6 regions (split s x gate g), each 32 rows x 512 k bf16, exact 1024B/row,
//    16B-slot XOR swizzle (slot ^ (n&7)) -> conflict-free ldmatrix.
#define W_REGION 32768
#define SW_BYTES (6 * W_REGION)           // 196608
#define OFF_SA   SW_BYTES                 // A double buffer: 2 x [2s][128m][64B]
#define SA_BUF   16384
#define SMEM_TOTAL (SW_BYTES + 2 * SA_BUF)  // 229376

// ---------------- asm helpers ----------------
__device__ __forceinline__ uint32_t smem_to_u32(const void* p) {
    uint32_t a;
    asm("{ .reg .u64 t; cvta.to.shared.u64 t, %1; cvt.u32.u64 %0, t; }" : "=r"(a) : "l"(p));
    return a;
}
__device__ __forceinline__ void mma16816(float* c, const unsigned* a, const unsigned* b) {
    asm volatile(
        "mma.sync.aligned.m16n8k16.row.col.f32.bf16.bf16.f32 "
        "{%0,%1,%2,%3}, {%4,%5,%6,%7}, {%8,%9}, {%0,%1,%2,%3};\n"
        : "+f"(c[0]), "+f"(c[1]), "+f"(c[2]), "+f"(c[3])
        : "r"(a[0]), "r"(a[1]), "r"(a[2]), "r"(a[3]), "r"(b[0]), "r"(b[1]));
}
__device__ __forceinline__ void ldsm4(uint32_t addr, uint32_t* r) {
    asm volatile("ldmatrix.sync.aligned.m8n8.x4.shared.b16 {%0,%1,%2,%3}, [%4];"
                 : "=r"(r[0]), "=r"(r[1]), "=r"(r[2]), "=r"(r[3]) : "r"(addr));
}
#define CP16(dst, src) asm volatile("cp.async.cg.shared.global [%0], [%1], 16;" :: "r"(dst), "l"(src))
#define CPCOMMIT()     asm volatile("cp.async.commit_group;" ::: "memory")
#define CPWAIT0()      asm volatile("cp.async.wait_group 0;" ::: "memory")

__device__ __forceinline__ void split_bf16(float v, bf16& hi, bf16& lo) {
    hi = __float2bfloat16(v);
    lo = __float2bfloat16(v - __bfloat162float(hi));
}

// ---------------- init ----------------
__global__ void k_zero() {
    int i = blockIdx.x * 1024 + threadIdx.x;   // 512x1024 = Bn*Dd
    g_hnT[i] = 0.0f;
    g_hh[i] = __float2bfloat16(0.0f);
    g_hl[i] = __float2bfloat16(0.0f);
    if (i == 0) g_bar = 0u;
}

__global__ void k_wsplit(const float* __restrict__ W, bf16* __restrict__ Wh, bf16* __restrict__ Wl) {
    size_t i = (size_t)blockIdx.x * 512 + threadIdx.x;
    split_bf16(W[i], Wh[i], Wl[i]);
}

// ---------------- embeddings ----------------
__global__ __launch_bounds__(256) void k_embed(
    const float* __restrict__ ext, const float* __restrict__ obs,
    const float* __restrict__ Wu, const float* __restrict__ bu,
    const float* __restrict__ Wx, const float* __restrict__ bx)
{
    int row0 = blockIdx.x * 4;
    __shared__ float s_e[4][INU];
    __shared__ float s_o[4][OUTd];
    int tid = threadIdx.x;
    if (tid < 4 * INU)  { int r = tid / INU,  k = tid % INU;  s_e[r][k] = ext[(size_t)(row0 + r) * (INU + 1) + k]; }
    if (tid < 4 * OUTd) { int r = tid / OUTd, k = tid % OUTd; s_o[r][k] = obs[(size_t)(row0 + r) * OUTd + k]; }
    __syncthreads();
    float bu_t = bu[tid];
    float bx_t = bx[tid];
    #pragma unroll
    for (int r = 0; r < 4; r++) {
        float au = bu_t;
        #pragma unroll
        for (int k = 0; k < INU; k++) au += s_e[r][k] * Wu[k * Hd + tid];
        float ax = bx_t;
        #pragma unroll
        for (int k = 0; k < OUTd; k++) ax += s_o[r][k] * Wx[k * Hd + tid];
        size_t base = (size_t)(row0 + r) * Dd;
        float vu = tanhf(au), vx = tanhf(ax);
        split_bf16(vu, g_Xh[base + tid],      g_Xl[base + tid]);
        split_bf16(vx, g_Xh[base + Hd + tid], g_Xl[base + Hd + tid]);
    }
}

// ---------------- grid barrier ----------------
__device__ __forceinline__ void gbar(unsigned target) {
    __syncthreads();
    if (threadIdx.x == 0) {
        __threadfence();
        atomicAdd(&g_bar, 1u);
        while (*((volatile unsigned*)&g_bar) < target) { }
        __threadfence();
    }
    __syncthreads();
}

// ---------------- W loader: 6 regions, 1024B/row, 16B-slot XOR swizzle ----------------
__device__ void load_Wsw(const bf16* __restrict__ Wh, const bf16* __restrict__ Wl,
                         int d0, char* sW, int tid) {
    #pragma unroll 4
    for (int it = 0; it < 48; it++) {
        int flat = tid + it * 256;            // uint4 index, 0..12287
        int reg = flat >> 11;                 // region 0..5 = s*3+g
        int rem = flat & 2047;
        int n    = rem >> 6;                  // row 0..31
        int slot = rem & 63;                  // 16B slot (8 bf16)
        int s = reg / 3, g = reg - s * 3;
        const bf16* W = s ? Wl : Wh;
        uint4 v = *(const uint4*)(W + (size_t)(g * Dd + d0 + n) * Dd + slot * 8);
        *(uint4*)(sW + reg * W_REGION + n * 1024 + ((slot ^ (n & 7)) << 4)) = v;
    }
}

// ---------------- GEMM: C[128m x 96n] = A[128,512] @ Wslice^T, split-bf16 x3 ----------------
// cp.async double-buffered A staging + ldmatrix fragments.
__device__ __forceinline__ void gemm_tile(
    const bf16* __restrict__ Ah, const bf16* __restrict__ Al,
    uint32_t sAu, uint32_t sWu, float acc[3][2][2][4], int tid,
    uint32_t aBase, uint32_t aSlotL, uint32_t aSw,
    uint32_t bBase, uint32_t bKh, uint32_t bSw)
{
    #pragma unroll
    for (int g = 0; g < 3; g++)
        #pragma unroll
        for (int i2 = 0; i2 < 2; i2++)
            #pragma unroll
            for (int j2 = 0; j2 < 2; j2++)
                #pragma unroll
                for (int e = 0; e < 4; e++) acc[g][i2][j2][e] = 0.0f;

    // per-thread fill slots (4 x 16B per buffer)
    uint32_t fd[4]; const bf16* fs[4];
    #pragma unroll
    for (int i = 0; i < 4; i++) {
        int flat = tid + i * 256;             // 0..1023
        int s = flat >> 9, rem = flat & 511;
        int m = rem >> 2, slot = rem & 3;
        fd[i] = sAu + s * 8192 + m * 64 + (((uint32_t)(slot ^ ((m >> 1) & 3))) << 4);
        fs[i] = (s ? Al : Ah) + (size_t)m * Dd + slot * 8;
    }
    // prologue: chunk 0 -> buf 0
    #pragma unroll
    for (int i = 0; i < 4; i++) CP16(fd[i], fs[i]);
    CPCOMMIT();

    for (int c = 0; c < 16; c++) {
        CPWAIT0();
        __syncthreads();
        if (c < 15) {
            uint32_t nb = ((uint32_t)(c + 1) & 1u) * SA_BUF;
            #pragma unroll
            for (int i = 0; i < 4; i++) CP16(fd[i] + nb, fs[i] + (c + 1) * 32);
            CPCOMMIT();
        }
        uint32_t ab = aBase + ((uint32_t)(c & 1)) * SA_BUF;
        #pragma unroll
        for (int ks8 = 0; ks8 <= 2; ks8 += 2) {
            uint32_t afr[2][2][4];
            #pragma unroll
            for (int i2 = 0; i2 < 2; i2++)
                #pragma unroll
                for (int s = 0; s < 2; s++)
                    ldsm4(ab + s * 8192 + i2 * 1024 + (((aSlotL + ks8) ^ aSw) << 4), afr[i2][s]);
            uint32_t bfr[3][2][4];
            uint32_t bslot = (uint32_t)(c * 4 + ks8) + bKh;
            #pragma unroll
            for (int g = 0; g < 3; g++)
                #pragma unroll
                for (int s = 0; s < 2; s++)
                    ldsm4(bBase + (s * 3 + g) * W_REGION + ((bslot ^ bSw) << 4), bfr[g][s]);
            #pragma unroll
            for (int g = 0; g < 3; g++)
                #pragma unroll
                for (int i2 = 0; i2 < 2; i2++)
                    #pragma unroll
                    for (int j2 = 0; j2 < 2; j2++) {
                        mma16816(acc[g][i2][j2], afr[i2][0], &bfr[g][0][j2 * 2]);  // ah*bh
                        mma16816(acc[g][i2][j2], afr[i2][0], &bfr[g][1][j2 * 2]);  // ah*bl
                        mma16816(acc[g][i2][j2], afr[i2][1], &bfr[g][0][j2 * 2]);  // al*bh
                    }
        }
    }
}

// ---------------- THE persistent kernel ----------------
__global__ void __launch_bounds__(256, 1) k_persist(
    const float* __restrict__ ext,
    const float* __restrict__ bih, const float* __restrict__ bhh,
    const float* __restrict__ W1, const float* __restrict__ b1,
    const float* __restrict__ W2, const float* __restrict__ b2)
{
    extern __shared__ char smem[];
    uint32_t sWu = smem_to_u32(smem);
    uint32_t sAu = sWu + OFF_SA;
    float* s_h  = (float*)(smem + OFF_SA);           // [8][260] (overlay on sA)
    float* s_z  = (float*)(smem + OFF_SA + 8320);    // [8][132]
    float* s_c  = (float*)(smem + OFF_SA + 12544);   // [8][130]
    float* s_dt = (float*)(smem + OFF_SA + 16704);   // [8]

    const int tid = threadIdx.x;
    const int wid = tid >> 5, lane = tid & 31;
    const int bid = blockIdx.x;
    const int dtile = bid & 15, mg = bid >> 4;
    const int d0 = dtile * 32;
    const int m0ode = bid * 8;
    const int warp_m = wid >> 1, warp_n = wid & 1;
    const int q = lane >> 2, tp = lane & 3;
    unsigned bar_t = 0;

    // ldmatrix per-lane constants
    const int aRow = warp_m * 32 + (lane & 7) + ((lane >> 3) & 1) * 8;
    const uint32_t aBase = sAu + (uint32_t)aRow * 64;
    const uint32_t aSlotL = (uint32_t)(lane >> 4);
    const uint32_t aSw = (uint32_t)((aRow >> 1) & 3);
    const int bRowN = warp_n * 16 + (lane & 7) + ((lane >> 4) & 1) * 8;
    const uint32_t bBase = sWu + (uint32_t)bRowN * 1024;
    const uint32_t bKh = (uint32_t)((lane >> 3) & 1);
    const uint32_t bSw = (uint32_t)(bRowN & 7);

    float acc[3][2][2][4];

    // per-thread bias values (d depends only on j2, eo)
    float bI[3][2][2], bH[3][2][2];
    #pragma unroll
    for (int g = 0; g < 3; g++)
        #pragma unroll
        for (int j2 = 0; j2 < 2; j2++)
            #pragma unroll
            for (int eo = 0; eo < 2; eo++) {
                int d = d0 + warp_n * 16 + j2 * 8 + tp * 2 + eo;
                bI[g][j2][eo] = bih[g * Dd + d];
                bH[g][j2][eo] = bhh[g * Dd + d];
            }

    // ======== Phase 1: gi = X @ W_ih^T + b_ih ========
    load_Wsw(g_Wih_h, g_Wih_l, d0, smem, tid);
    __syncthreads();
    for (int t = 0; t < 127; t++) {
        const bf16* Ah = g_Xh + ((size_t)t * Bn + mg * 128) * Dd;
        const bf16* Al = g_Xl + ((size_t)t * Bn + mg * 128) * Dd;
        gemm_tile(Ah, Al, sAu, sWu, acc, tid, aBase, aSlotL, aSw, bBase, bKh, bSw);
        float* giT = g_giT + (size_t)t * G3 * Bn;
        #pragma unroll
        for (int i2 = 0; i2 < 2; i2++)
            #pragma unroll
            for (int j2 = 0; j2 < 2; j2++)
                #pragma unroll
                for (int e = 0; e < 4; e++) {
                    int b = mg * 128 + warp_m * 32 + i2 * 16 + q + (e >> 1) * 8;
                    int d = d0 + warp_n * 16 + j2 * 8 + tp * 2 + (e & 1);
                    #pragma unroll
                    for (int g = 0; g < 3; g++)
                        giT[(size_t)(g * Dd + d) * Bn + b] = acc[g][i2][j2][e] + bI[g][j2][e & 1];
                }
    }

    // ======== Phase 2: recurrent loop ========
    __syncthreads();                      // all warps done reading W_ih smem
    load_Wsw(g_Whh_h, g_Whh_l, d0, smem, tid);
    bar_t += NBLK; gbar(bar_t);           // gi written everywhere; W_hh loaded

    for (int t = 0; t < 127; t++) {
        gemm_tile(g_hh + (size_t)mg * 128 * Dd, g_hl + (size_t)mg * 128 * Dd,
                  sAu, sWu, acc, tid, aBase, aSlotL, aSw, bBase, bKh, bSw);
        // fused GRU gates epilogue -> g_tmpT
        const float* giT = g_giT + (size_t)t * G3 * Bn;
        const float* hpT = g_hnT + (size_t)t * Dd * Bn;
        #pragma unroll
        for (int i2 = 0; i2 < 2; i2++)
            #pragma unroll
            for (int j2 = 0; j2 < 2; j2++)
                #pragma unroll
                for (int e = 0; e < 4; e++) {
                    int b = mg * 128 + warp_m * 32 + i2 * 16 + q + (e >> 1) * 8;
                    int d = d0 + warp_n * 16 + j2 * 8 + tp * 2 + (e & 1);
                    float gR = acc[0][i2][j2][e] + bH[0][j2][e & 1];
                    float gZ = acc[1][i2][j2][e] + bH[1][j2][e & 1];
                    float gN = acc[2][i2][j2][e] + bH[2][j2][e & 1];
                    float giR = __ldcg(&giT[(size_t)d * Bn + b]);
                    float giZ = __ldcg(&giT[(size_t)(Dd + d) * Bn + b]);
                    float giN = __ldcg(&giT[(size_t)(2 * Dd + d) * Bn + b]);
                    float r = 1.0f / (1.0f + __expf(-(giR + gR)));
                    float z = 1.0f / (1.0f + __expf(-(giZ + gZ)));
                    float nn = tanhf(giN + r * gN);
                    float hp = __ldcg(&hpT[(size_t)d * Bn + b]);
                    g_tmpT[(size_t)d * Bn + b] = (1.0f - z) * nn + z * hp;
                }
        bar_t += NBLK; gbar(bar_t);

        // ---- ODE MLP + Euler for rows m0ode..m0ode+7 ----
        #pragma unroll
        for (int i = 0; i < 8; i++) {
            int idx = tid + i * 256;
            int r = idx & 7, cc = idx >> 3;           // cc 0..255
            s_h[r * 260 + cc] = __ldcg(&g_tmpT[(size_t)cc * Bn + m0ode + r]);
        }
        if (tid < 8) s_dt[tid] = ext[((size_t)t * Bn + m0ode + tid) * (INU + 1) + INU];
        __syncthreads();
        {   // z = tanh(h @ W1 + b1); 4 rows per thread
            int col = tid & 127, rg = tid >> 7;
            float a0 = b1[col], a1 = a0, a2 = a0, a3 = a0;
            #pragma unroll 4
            for (int k = 0; k < Hd; k++) {
                float w = W1[k * ODEH + col];
                a0 += s_h[(rg * 4 + 0) * 260 + k] * w;
                a1 += s_h[(rg * 4 + 1) * 260 + k] * w;
                a2 += s_h[(rg * 4 + 2) * 260 + k] * w;
                a3 += s_h[(rg * 4 + 3) * 260 + k] * w;
            }
            s_z[(rg * 4 + 0) * 132 + col] = tanhf(a0);
            s_z[(rg * 4 + 1) * 132 + col] = tanhf(a1);
            s_z[(rg * 4 + 2) * 132 + col] = tanhf(a2);
            s_z[(rg * 4 + 3) * 132 + col] = tanhf(a3);
        }
        __syncthreads();
        float hnew[8];
        {   // f = z @ W2 + b2 ; hnew = h + dt*f ; write h splits (m-major)
            int col = tid;
            float f[8];
            float bb = b2[col];
            #pragma unroll
            for (int r = 0; r < 8; r++) f[r] = bb;
            #pragma unroll 4
            for (int k = 0; k < ODEH; k++) {
                float w = W2[k * Hd + col];
                #pragma unroll
                for (int r = 0; r < 8; r++) f[r] += s_z[r * 132 + k] * w;
            }
            #pragma unroll
            for (int r = 0; r < 8; r++) {
                hnew[r] = s_h[r * 260 + col] + s_dt[r] * f[r];
                bf16 hi, lo; split_bf16(hnew[r], hi, lo);
                g_hh[(size_t)(m0ode + r) * Dd + col] = hi;
                g_hl[(size_t)(m0ode + r) * Dd + col] = lo;
            }
        }
        __syncthreads();
        {   int col = tid;
            #pragma unroll
            for (int r = 0; r < 8; r++) s_h[r * 260 + col] = hnew[r];
        }
        __syncthreads();
        float* hnT1 = g_hnT + (size_t)(t + 1) * Dd * Bn;
        #pragma unroll
        for (int i = 0; i < 8; i++) {
            int idx = tid + i * 256;
            int r = idx & 7, cc = idx >> 3;
            hnT1[(size_t)cc * Bn + m0ode + r] = s_h[r * 260 + cc];
        }
        #pragma unroll
        for (int ch = 0; ch < 2; ch++) {              // c passthrough + splits
            int cbase = Hd + ch * 128;
            #pragma unroll
            for (int i = 0; i < 4; i++) {
                int idx = tid + i * 256;
                int r = idx & 7, cl = idx >> 3;
                float x = __ldcg(&g_tmpT[(size_t)(cbase + cl) * Bn + m0ode + r]);
                hnT1[(size_t)(cbase + cl) * Bn + m0ode + r] = x;
                s_c[r * 130 + cl] = x;
            }
            __syncthreads();
            #pragma unroll
            for (int i = 0; i < 4; i++) {
                int idx = tid + i * 256;
                int r = idx >> 7, cl = idx & 127;
                float x = s_c[r * 130 + cl];
                bf16 hi, lo; split_bf16(x, hi, lo);
                g_hh[(size_t)(m0ode + r) * Dd + cbase + cl] = hi;
                g_hl[(size_t)(m0ode + r) * Dd + cbase + cl] = lo;
            }
            __syncthreads();
        }
        bar_t += NBLK; gbar(bar_t);
    }
}

// ---------------- output projection ----------------
__global__ __launch_bounds__(256) void k_out(
    const float* __restrict__ WLy, const float* __restrict__ bLy,
    float* __restrict__ out)
{
    __shared__ float s_w[Dd * OUTd];   // 32 KB
    int t = blockIdx.x >> 3;
    int b0 = (blockIdx.x & 7) * 128;
    int tid = threadIdx.x;
    #pragma unroll
    for (int i = 0; i < 32; i++) s_w[tid + i * 256] = WLy[tid + i * 256];
    __syncthreads();
    int b = b0 + (tid >> 1);
    int oh = (tid & 1) * 8;
    const float* hp = g_hnT + (size_t)t * Dd * Bn;
    float a[8];
    #pragma unroll
    for (int j = 0; j < 8; j++) a[j] = bLy[oh + j];
    #pragma unroll 4
    for (int k = 0; k < Dd; k++) {
        float v = __ldg(&hp[(size_t)k * Bn + b]);
        #pragma unroll
        for (int j = 0; j < 8; j++) a[j] += v * s_w[k * OUTd + oh + j];
    }
    float* op = out + ((size_t)t * Bn + b) * OUTd + oh;
    *(float4*)(op)     = make_float4(a[0], a[1], a[2], a[3]);
    *(float4*)(op + 4) = make_float4(a[4], a[5], a[6], a[7]);
}

// ---------------- launch ----------------
extern "C" void kernel_launch(void* const* d_in, const int* in_sizes, int n_in,
                              void* d_out, int out_size)
{
    const float* ext = (const float*)d_in[0];
    const float* obs = (const float*)d_in[1];
    const float* Wu  = (const float*)d_in[2];
    const float* bu  = (const float*)d_in[3];
    const float* Wx  = (const float*)d_in[4];
    const float* bx  = (const float*)d_in[5];
    const float* Wih = (const float*)d_in[6];
    const float* Whh = (const float*)d_in[7];
    const float* bih = (const float*)d_in[8];
    const float* bhh = (const float*)d_in[9];
    const float* W1  = (const float*)d_in[10];
    const float* b1  = (const float*)d_in[11];
    const float* W2  = (const float*)d_in[12];
    const float* b2  = (const float*)d_in[13];
    const float* WLy = (const float*)d_in[14];
    const float* bLy = (const float*)d_in[15];
    float* out = (float*)d_out;

    bf16 *p_Wih_h, *p_Wih_l, *p_Whh_h, *p_Whh_l;
    cudaGetSymbolAddress((void**)&p_Wih_h, g_Wih_h);
    cudaGetSymbolAddress((void**)&p_Wih_l, g_Wih_l);
    cudaGetSymbolAddress((void**)&p_Whh_h, g_Whh_h);
    cudaGetSymbolAddress((void**)&p_Whh_l, g_Whh_l);

    cudaFuncSetAttribute(k_persist, cudaFuncAttributeMaxDynamicSharedMemorySize, SMEM_TOTAL);

    k_zero<<<512, 1024>>>();
    k_wsplit<<<G3, 512>>>(Wih, p_Wih_h, p_Wih_l);
    k_wsplit<<<G3, 512>>>(Whh, p_Whh_h, p_Whh_l);
    k_embed<<<ROWS / 4, 256>>>(ext, obs, Wu, bu, Wx, bx);

    k_persist<<<NBLK, 256, SMEM_TOTAL>>>(ext, bih, bhh, W1, b1, W2, b2);

    k_out<<<Ln * 8, 256>>>(WLy, bLy, out);
}

// round 10
// speedup vs baseline: 2.6203x; 1.1928x over previous
#include <cuda_runtime.h>
#include <cuda_fp16.h>
#include <cstdint>

// Problem constants
#define Ln   128
#define Bn   1024
#define Hd   256
#define Dd   512
#define G3   1536
#define ODEH 128
#define INU  32
#define OUTd 16
#define ROWS (Ln * Bn)  // 131072
#define NBLK 128        // persistent grid, 1 CTA/SM via smem

typedef __half fp16;

// ---------------- scratch (device globals; no allocs allowed) ----------------
__device__ fp16  g_Xh [(size_t)ROWS * Dd];     // embeddings hi split (m-major)
__device__ fp16  g_Xl [(size_t)ROWS * Dd];     // embeddings lo split
__device__ float g_giT[(size_t)Ln * G3 * Bn];  // gi TRANSPOSED [t][gate*512+d][b]
__device__ float g_hnT[(size_t)Ln * Dd * Bn];  // hn history TRANSPOSED [t][d][b]
__device__ float g_tmpT[(size_t)Dd * Bn];      // GRU out TRANSPOSED [d][b]
__device__ fp16  g_hh [Bn * Dd], g_hl[Bn * Dd];  // current h splits (m-major)
__device__ fp16  g_Wih[G3 * Dd];               // W_ih fp16
__device__ fp16  g_Whh[G3 * Dd];               // W_hh fp16
__device__ unsigned g_barG[8 * 32];            // per-mg group barrier counters (128B apart)

// ---------------- smem map ----------------
// W: 3 regions (one per gate), each 32 rows x 512 k fp16, 1024B/row,
//    16B-slot XOR swizzle (slot ^ (n&7)) -> conflict-free ldmatrix.
#define W_REGION 32768
#define SW_BYTES (3 * W_REGION)           // 98304
#define OFF_SA   SW_BYTES                 // A double buffer: 2 x [2s][128m][64B]
#define SA_BUF   16384
#define SMEM_TOTAL (SW_BYTES + 2 * SA_BUF)  // 131072

// ---------------- asm helpers ----------------
__device__ __forceinline__ uint32_t smem_to_u32(const void* p) {
    uint32_t a;
    asm("{ .reg .u64 t; cvta.to.shared.u64 t, %1; cvt.u32.u64 %0, t; }" : "=r"(a) : "l"(p));
    return a;
}
__device__ __forceinline__ void mma16816(float* c, const unsigned* a, const unsigned* b) {
    asm volatile(
        "mma.sync.aligned.m16n8k16.row.col.f32.f16.f16.f32 "
        "{%0,%1,%2,%3}, {%4,%5,%6,%7}, {%8,%9}, {%0,%1,%2,%3};\n"
        : "+f"(c[0]), "+f"(c[1]), "+f"(c[2]), "+f"(c[3])
        : "r"(a[0]), "r"(a[1]), "r"(a[2]), "r"(a[3]), "r"(b[0]), "r"(b[1]));
}
__device__ __forceinline__ void ldsm4(uint32_t addr, uint32_t* r) {
    asm volatile("ldmatrix.sync.aligned.m8n8.x4.shared.b16 {%0,%1,%2,%3}, [%4];"
                 : "=r"(r[0]), "=r"(r[1]), "=r"(r[2]), "=r"(r[3]) : "r"(addr));
}
#define CP16(dst, src) asm volatile("cp.async.cg.shared.global [%0], [%1], 16;" :: "r"(dst), "l"(src))
#define CPCOMMIT()     asm volatile("cp.async.commit_group;" ::: "memory")
#define CPWAIT0()      asm volatile("cp.async.wait_group 0;" ::: "memory")

__device__ __forceinline__ void split_fp16(float v, fp16& hi, fp16& lo) {
    hi = __float2half(v);
    lo = __float2half(v - __half2float(hi));
}

// ---------------- init ----------------
__global__ void k_zero() {
    int i = blockIdx.x * 1024 + threadIdx.x;   // 512x1024 = Bn*Dd
    g_hnT[i] = 0.0f;
    g_hh[i] = __float2half(0.0f);
    g_hl[i] = __float2half(0.0f);
    if (i < 8 * 32) g_barG[i] = 0u;
}

__global__ void k_wconv(const float* __restrict__ W, fp16* __restrict__ Wo) {
    size_t i = (size_t)blockIdx.x * 512 + threadIdx.x;
    Wo[i] = __float2half(W[i]);
}

// ---------------- embeddings ----------------
__global__ __launch_bounds__(256) void k_embed(
    const float* __restrict__ ext, const float* __restrict__ obs,
    const float* __restrict__ Wu, const float* __restrict__ bu,
    const float* __restrict__ Wx, const float* __restrict__ bx)
{
    int row0 = blockIdx.x * 4;
    __shared__ float s_e[4][INU];
    __shared__ float s_o[4][OUTd];
    int tid = threadIdx.x;
    if (tid < 4 * INU)  { int r = tid / INU,  k = tid % INU;  s_e[r][k] = ext[(size_t)(row0 + r) * (INU + 1) + k]; }
    if (tid < 4 * OUTd) { int r = tid / OUTd, k = tid % OUTd; s_o[r][k] = obs[(size_t)(row0 + r) * OUTd + k]; }
    __syncthreads();
    float bu_t = bu[tid];
    float bx_t = bx[tid];
    #pragma unroll
    for (int r = 0; r < 4; r++) {
        float au = bu_t;
        #pragma unroll
        for (int k = 0; k < INU; k++) au += s_e[r][k] * Wu[k * Hd + tid];
        float ax = bx_t;
        #pragma unroll
        for (int k = 0; k < OUTd; k++) ax += s_o[r][k] * Wx[k * Hd + tid];
        size_t base = (size_t)(row0 + r) * Dd;
        float vu = tanhf(au), vx = tanhf(ax);
        split_fp16(vu, g_Xh[base + tid],      g_Xl[base + tid]);
        split_fp16(vx, g_Xh[base + Hd + tid], g_Xl[base + Hd + tid]);
    }
}

// ---------------- group barrier (16 blocks sharing mg) ----------------
__device__ __forceinline__ void gbarg(unsigned* ctr, unsigned target) {
    __syncthreads();
    if (threadIdx.x == 0) {
        __threadfence();
        atomicAdd(ctr, 1u);
        while (*((volatile unsigned*)ctr) < target) { }
        __threadfence();
    }
    __syncthreads();
}

// ---------------- W loader: 3 regions, 1024B/row, 16B-slot XOR swizzle ----------------
__device__ void load_Wsw(const fp16* __restrict__ W, int d0, char* sW, int tid) {
    #pragma unroll 4
    for (int it = 0; it < 24; it++) {
        int flat = tid + it * 256;            // uint4 index, 0..6143
        int g = flat >> 11;                   // region 0..2 (gate)
        int rem = flat & 2047;
        int n    = rem >> 6;                  // row 0..31
        int slot = rem & 63;                  // 16B slot (8 fp16)
        uint4 v = *(const uint4*)(W + (size_t)(g * Dd + d0 + n) * Dd + slot * 8);
        *(uint4*)(sW + g * W_REGION + n * 1024 + ((slot ^ (n & 7)) << 4)) = v;
    }
}

// ---------------- GEMM: C[128m x 96n] = A[128,512] @ Wslice^T, fp16 2-term ----------------
__device__ __forceinline__ void gemm_tile(
    const fp16* __restrict__ Ah, const fp16* __restrict__ Al,
    uint32_t sAu, float acc[3][2][2][4], int tid,
    uint32_t aBase, uint32_t aSlotL, uint32_t aSw,
    uint32_t bBase, uint32_t bKh, uint32_t bSw)
{
    #pragma unroll
    for (int g = 0; g < 3; g++)
        #pragma unroll
        for (int i2 = 0; i2 < 2; i2++)
            #pragma unroll
            for (int j2 = 0; j2 < 2; j2++)
                #pragma unroll
                for (int e = 0; e < 4; e++) acc[g][i2][j2][e] = 0.0f;

    // per-thread fill slots (4 x 16B per buffer)
    uint32_t fd[4]; const fp16* fs[4];
    #pragma unroll
    for (int i = 0; i < 4; i++) {
        int flat = tid + i * 256;             // 0..1023
        int s = flat >> 9, rem = flat & 511;
        int m = rem >> 2, slot = rem & 3;
        fd[i] = sAu + s * 8192 + m * 64 + (((uint32_t)(slot ^ ((m >> 1) & 3))) << 4);
        fs[i] = (s ? Al : Ah) + (size_t)m * Dd + slot * 8;
    }
    // prologue: chunk 0 -> buf 0
    #pragma unroll
    for (int i = 0; i < 4; i++) CP16(fd[i], fs[i]);
    CPCOMMIT();

    for (int c = 0; c < 16; c++) {
        CPWAIT0();
        __syncthreads();
        if (c < 15) {
            uint32_t nb = ((uint32_t)(c + 1) & 1u) * SA_BUF;
            #pragma unroll
            for (int i = 0; i < 4; i++) CP16(fd[i] + nb, fs[i] + (c + 1) * 32);
            CPCOMMIT();
        }
        uint32_t ab = aBase + ((uint32_t)(c & 1)) * SA_BUF;
        #pragma unroll
        for (int ks8 = 0; ks8 <= 2; ks8 += 2) {
            uint32_t afr[2][2][4];
            #pragma unroll
            for (int i2 = 0; i2 < 2; i2++)
                #pragma unroll
                for (int s = 0; s < 2; s++)
                    ldsm4(ab + s * 8192 + i2 * 1024 + (((aSlotL + ks8) ^ aSw) << 4), afr[i2][s]);
            uint32_t bfr[3][4];
            uint32_t bslot = (uint32_t)(c * 4 + ks8) + bKh;
            #pragma unroll
            for (int g = 0; g < 3; g++)
                ldsm4(bBase + g * W_REGION + ((bslot ^ bSw) << 4), bfr[g]);
            #pragma unroll
            for (int g = 0; g < 3; g++)
                #pragma unroll
                for (int i2 = 0; i2 < 2; i2++)
                    #pragma unroll
                    for (int j2 = 0; j2 < 2; j2++) {
                        mma16816(acc[g][i2][j2], afr[i2][0], &bfr[g][j2 * 2]);  // ah*b
                        mma16816(acc[g][i2][j2], afr[i2][1], &bfr[g][j2 * 2]);  // al*b
                    }
        }
    }
}

// ---------------- THE persistent kernel ----------------
__global__ void __launch_bounds__(256, 1) k_persist(
    const float* __restrict__ ext,
    const float* __restrict__ bih, const float* __restrict__ bhh,
    const float* __restrict__ W1, const float* __restrict__ b1,
    const float* __restrict__ W2, const float* __restrict__ b2)
{
    extern __shared__ char smem[];
    uint32_t sWu = smem_to_u32(smem);
    uint32_t sAu = sWu + OFF_SA;
    float* s_h  = (float*)(smem + OFF_SA);            // [8][260]   (overlay on sA)
    float* s_zp = (float*)(smem + OFF_SA + 8320);     // [2][8][132] partials -> z in [0]
    float* s_c  = (float*)(smem + OFF_SA + 16768);    // [8][130]
    float* s_dt = (float*)(smem + OFF_SA + 20928);    // [8]

    const int tid = threadIdx.x;
    const int wid = tid >> 5, lane = tid & 31;
    const int bid = blockIdx.x;
    const int dtile = bid & 15, mg = bid >> 4;
    const int d0 = dtile * 32;
    const int m0ode = bid * 8;
    const int warp_m = wid >> 1, warp_n = wid & 1;
    const int q = lane >> 2, tp = lane & 3;
    unsigned* gctr = &g_barG[mg * 32];
    unsigned bar_t = 0;

    // ldmatrix per-lane constants
    const int aRow = warp_m * 32 + (lane & 7) + ((lane >> 3) & 1) * 8;
    const uint32_t aBase = sAu + (uint32_t)aRow * 64;
    const uint32_t aSlotL = (uint32_t)(lane >> 4);
    const uint32_t aSw = (uint32_t)((aRow >> 1) & 3);
    const int bRowN = warp_n * 16 + (lane & 7) + ((lane >> 4) & 1) * 8;
    const uint32_t bBase = sWu + (uint32_t)bRowN * 1024;
    const uint32_t bKh = (uint32_t)((lane >> 3) & 1);
    const uint32_t bSw = (uint32_t)(bRowN & 7);

    float acc[3][2][2][4];

    // per-thread bias values (d depends only on j2, eo)
    float bI[3][2][2], bH[3][2][2];
    #pragma unroll
    for (int g = 0; g < 3; g++)
        #pragma unroll
        for (int j2 = 0; j2 < 2; j2++)
            #pragma unroll
            for (int eo = 0; eo < 2; eo++) {
                int d = d0 + warp_n * 16 + j2 * 8 + tp * 2 + eo;
                bI[g][j2][eo] = bih[g * Dd + d];
                bH[g][j2][eo] = bhh[g * Dd + d];
            }

    // ======== Phase 1: gi = X @ W_ih^T + b_ih ========
    load_Wsw(g_Wih, d0, smem, tid);
    __syncthreads();
    for (int t = 0; t < 127; t++) {
        const fp16* Ah = g_Xh + ((size_t)t * Bn + mg * 128) * Dd;
        const fp16* Al = g_Xl + ((size_t)t * Bn + mg * 128) * Dd;
        gemm_tile(Ah, Al, sAu, acc, tid, aBase, aSlotL, aSw, bBase, bKh, bSw);
        float* giT = g_giT + (size_t)t * G3 * Bn;
        #pragma unroll
        for (int i2 = 0; i2 < 2; i2++)
            #pragma unroll
            for (int j2 = 0; j2 < 2; j2++)
                #pragma unroll
                for (int e = 0; e < 4; e++) {
                    int b = mg * 128 + warp_m * 32 + i2 * 16 + q + (e >> 1) * 8;
                    int d = d0 + warp_n * 16 + j2 * 8 + tp * 2 + (e & 1);
                    #pragma unroll
                    for (int g = 0; g < 3; g++)
                        giT[(size_t)(g * Dd + d) * Bn + b] = acc[g][i2][j2][e] + bI[g][j2][e & 1];
                }
    }

    // ======== Phase 2: recurrent loop (group-local synchronization only) ========
    __syncthreads();                      // all warps done reading W_ih smem
    load_Wsw(g_Whh, d0, smem, tid);
    __syncthreads();

    for (int t = 0; t < 127; t++) {
        gemm_tile(g_hh + (size_t)mg * 128 * Dd, g_hl + (size_t)mg * 128 * Dd,
                  sAu, acc, tid, aBase, aSlotL, aSw, bBase, bKh, bSw);
        // fused GRU gates epilogue -> g_tmpT
        const float* giT = g_giT + (size_t)t * G3 * Bn;
        const float* hpT = g_hnT + (size_t)t * Dd * Bn;
        #pragma unroll
        for (int i2 = 0; i2 < 2; i2++)
            #pragma unroll
            for (int j2 = 0; j2 < 2; j2++)
                #pragma unroll
                for (int e = 0; e < 4; e++) {
                    int b = mg * 128 + warp_m * 32 + i2 * 16 + q + (e >> 1) * 8;
                    int d = d0 + warp_n * 16 + j2 * 8 + tp * 2 + (e & 1);
                    float gR = acc[0][i2][j2][e] + bH[0][j2][e & 1];
                    float gZ = acc[1][i2][j2][e] + bH[1][j2][e & 1];
                    float gN = acc[2][i2][j2][e] + bH[2][j2][e & 1];
                    float giR = __ldcg(&giT[(size_t)d * Bn + b]);
                    float giZ = __ldcg(&giT[(size_t)(Dd + d) * Bn + b]);
                    float giN = __ldcg(&giT[(size_t)(2 * Dd + d) * Bn + b]);
                    float r = 1.0f / (1.0f + __expf(-(giR + gR)));
                    float z = 1.0f / (1.0f + __expf(-(giZ + gZ)));
                    float nn = tanhf(giN + r * gN);
                    float hp = __ldcg(&hpT[(size_t)d * Bn + b]);
                    g_tmpT[(size_t)d * Bn + b] = (1.0f - z) * nn + z * hp;
                }
        bar_t += 16; gbarg(gctr, bar_t);   // group's epilogues done

        // ---- ODE MLP + Euler for rows m0ode..m0ode+7 ----
        #pragma unroll
        for (int i = 0; i < 8; i++) {
            int idx = tid + i * 256;
            int r = idx & 7, cc = idx >> 3;           // cc 0..255
            s_h[r * 260 + cc] = __ldcg(&g_tmpT[(size_t)cc * Bn + m0ode + r]);
        }
        if (tid < 8) s_dt[tid] = ext[((size_t)t * Bn + m0ode + tid) * (INU + 1) + INU];
        __syncthreads();
        {   // z = tanh(h @ W1 + b1), k-split across warp halves (W1 read exactly once)
            int col = tid & 127, half = tid >> 7;
            float a[8];
            #pragma unroll
            for (int r = 0; r < 8; r++) a[r] = 0.0f;
            const int kb = half * 128;
            #pragma unroll 4
            for (int k = 0; k < 128; k++) {
                float w = W1[(kb + k) * ODEH + col];
                #pragma unroll
                for (int r = 0; r < 8; r++) a[r] += s_h[r * 260 + kb + k] * w;
            }
            #pragma unroll
            for (int r = 0; r < 8; r++) s_zp[half * 1056 + r * 132 + col] = a[r];
        }
        __syncthreads();
        #pragma unroll
        for (int i = 0; i < 4; i++) {                 // combine halves + tanh (in-place into s_zp[0])
            int idx = tid + i * 256;
            int r = idx >> 7, c = idx & 127;
            s_zp[r * 132 + c] = tanhf(s_zp[r * 132 + c] + s_zp[1056 + r * 132 + c] + b1[c]);
        }
        __syncthreads();
        float hnew[8];
        {   // f = z @ W2 + b2 ; hnew = h + dt*f ; write h splits (m-major)
            int col = tid;
            float f[8];
            float bb = b2[col];
            #pragma unroll
            for (int r = 0; r < 8; r++) f[r] = bb;
            #pragma unroll 4
            for (int k = 0; k < ODEH; k++) {
                float w = W2[k * Hd + col];
                #pragma unroll
                for (int r = 0; r < 8; r++) f[r] += s_zp[r * 132 + k] * w;
            }
            #pragma unroll
            for (int r = 0; r < 8; r++) {
                hnew[r] = s_h[r * 260 + col] + s_dt[r] * f[r];
                fp16 hi, lo; split_fp16(hnew[r], hi, lo);
                g_hh[(size_t)(m0ode + r) * Dd + col] = hi;
                g_hl[(size_t)(m0ode + r) * Dd + col] = lo;
            }
        }
        __syncthreads();
        {   int col = tid;
            #pragma unroll
            for (int r = 0; r < 8; r++) s_h[r * 260 + col] = hnew[r];
        }
        __syncthreads();
        float* hnT1 = g_hnT + (size_t)(t + 1) * Dd * Bn;
        #pragma unroll
        for (int i = 0; i < 8; i++) {
            int idx = tid + i * 256;
            int r = idx & 7, cc = idx >> 3;
            hnT1[(size_t)cc * Bn + m0ode + r] = s_h[r * 260 + cc];
        }
        #pragma unroll
        for (int ch = 0; ch < 2; ch++) {              // c passthrough + splits
            int cbase = Hd + ch * 128;
            #pragma unroll
            for (int i = 0; i < 4; i++) {
                int idx = tid + i * 256;
                int r = idx & 7, cl = idx >> 3;
                float x = __ldcg(&g_tmpT[(size_t)(cbase + cl) * Bn + m0ode + r]);
                hnT1[(size_t)(cbase + cl) * Bn + m0ode + r] = x;
                s_c[r * 130 + cl] = x;
            }
            __syncthreads();
            #pragma unroll
            for (int i = 0; i < 4; i++) {
                int idx = tid + i * 256;
                int r = idx >> 7, cl = idx & 127;
                float x = s_c[r * 130 + cl];
                fp16 hi, lo; split_fp16(x, hi, lo);
                g_hh[(size_t)(m0ode + r) * Dd + cbase + cl] = hi;
                g_hl[(size_t)(m0ode + r) * Dd + cbase + cl] = lo;
            }
            __syncthreads();
        }
        bar_t += 16; gbarg(gctr, bar_t);   // group's ODE done -> next GEMM may read g_hh
    }
}

// ---------------- output projection ----------------
__global__ __launch_bounds__(256) void k_out(
    const float* __restrict__ WLy, const float* __restrict__ bLy,
    float* __restrict__ out)
{
    __shared__ float s_w[Dd * OUTd];   // 32 KB
    int t = blockIdx.x >> 3;
    int b0 = (blockIdx.x & 7) * 128;
    int tid = threadIdx.x;
    #pragma unroll
    for (int i = 0; i < 32; i++) s_w[tid + i * 256] = WLy[tid + i * 256];
    __syncthreads();
    int b = b0 + (tid >> 1);
    int oh = (tid & 1) * 8;
    const float* hp = g_hnT + (size_t)t * Dd * Bn;
    float a[8];
    #pragma unroll
    for (int j = 0; j < 8; j++) a[j] = bLy[oh + j];
    #pragma unroll 4
    for (int k = 0; k < Dd; k++) {
        float v = __ldg(&hp[(size_t)k * Bn + b]);
        #pragma unroll
        for (int j = 0; j < 8; j++) a[j] += v * s_w[k * OUTd + oh + j];
    }
    float* op = out + ((size_t)t * Bn + b) * OUTd + oh;
    *(float4*)(op)     = make_float4(a[0], a[1], a[2], a[3]);
    *(float4*)(op + 4) = make_float4(a[4], a[5], a[6], a[7]);
}

// ---------------- launch ----------------
extern "C" void kernel_launch(void* const* d_in, const int* in_sizes, int n_in,
                              void* d_out, int out_size)
{
    const float* ext = (const float*)d_in[0];
    const float* obs = (const float*)d_in[1];
    const float* Wu  = (const float*)d_in[2];
    const float* bu  = (const float*)d_in[3];
    const float* Wx  = (const float*)d_in[4];
    const float* bx  = (const float*)d_in[5];
    const float* Wih = (const float*)d_in[6];
    const float* Whh = (const float*)d_in[7];
    const float* bih = (const float*)d_in[8];
    const float* bhh = (const float*)d_in[9];
    const float* W1  = (const float*)d_in[10];
    const float* b1  = (const float*)d_in[11];
    const float* W2  = (const float*)d_in[12];
    const float* b2  = (const float*)d_in[13];
    const float* WLy = (const float*)d_in[14];
    const float* bLy = (const float*)d_in[15];
    float* out = (float*)d_out;

    fp16 *p_Wih, *p_Whh;
    cudaGetSymbolAddress((void**)&p_Wih, g_Wih);
    cudaGetSymbolAddress((void**)&p_Whh, g_Whh);

    cudaFuncSetAttribute(k_persist, cudaFuncAttributeMaxDynamicSharedMemorySize, SMEM_TOTAL);

    k_zero<<<512, 1024>>>();
    k_wconv<<<G3, 512>>>(Wih, p_Wih);
    k_wconv<<<G3, 512>>>(Whh, p_Whh);
    k_embed<<<ROWS / 4, 256>>>(ext, obs, Wu, bu, Wx, bx);

    k_persist<<<NBLK, 256, SMEM_TOTAL>>>(ext, bih, bhh, W1, b1, W2, b2);

    k_out<<<Ln * 8, 256>>>(WLy, bLy, out);
}

// round 12
// speedup vs baseline: 2.8949x; 1.1048x over previous
#include <cuda_runtime.h>
#include <cuda_fp16.h>
#include <cstdint>

// Problem constants
#define Ln   128
#define Bn   1024
#define Hd   256
#define Dd   512
#define G3   1536
#define ODEH 128
#define INU  32
#define OUTd 16
#define ROWS (Ln * Bn)  // 131072
#define NBLK 128        // persistent grid, 1 CTA/SM via smem

typedef __half fp16;

// ---------------- scratch (device globals; no allocs allowed) ----------------
__device__ fp16  g_Xh [(size_t)ROWS * Dd];     // embeddings fp16 (m-major)
__device__ float g_giT[(size_t)Ln * G3 * Bn];  // gi TRANSPOSED [t][gate*512+d][b]
__device__ float g_hnT[(size_t)Ln * Dd * Bn];  // hn history TRANSPOSED [t][d][b]
__device__ float g_tmpT[(size_t)Dd * Bn];      // GRU out TRANSPOSED [d][b]
__device__ fp16  g_hh [Bn * Dd], g_hl[Bn * Dd];  // current h splits (m-major)
__device__ fp16  g_Wih[G3 * Dd];               // W_ih fp16
__device__ fp16  g_Whh[G3 * Dd];               // W_hh fp16
__device__ unsigned g_barG[8 * 32];            // per-mg group barrier counters (128B apart)

// ---------------- smem map ----------------
// W: 3 regions (one per gate), each 32 rows x 512 k fp16, 1024B/row,
//    16B-slot XOR swizzle (slot ^ (n&7)) -> conflict-free ldmatrix.
#define W_REGION 32768
#define SW_BYTES (3 * W_REGION)           // 98304
#define OFF_SA   SW_BYTES
// A double buffer: 2 x (NS * 16384); max NS=2 -> 64KB
#define SMEM_TOTAL (SW_BYTES + 65536)     // 163840

// ---------------- asm helpers ----------------
__device__ __forceinline__ uint32_t smem_to_u32(const void* p) {
    uint32_t a;
    asm("{ .reg .u64 t; cvta.to.shared.u64 t, %1; cvt.u32.u64 %0, t; }" : "=r"(a) : "l"(p));
    return a;
}
__device__ __forceinline__ void mma16816(float* c, const unsigned* a, const unsigned* b) {
    asm volatile(
        "mma.sync.aligned.m16n8k16.row.col.f32.f16.f16.f32 "
        "{%0,%1,%2,%3}, {%4,%5,%6,%7}, {%8,%9}, {%0,%1,%2,%3};\n"
        : "+f"(c[0]), "+f"(c[1]), "+f"(c[2]), "+f"(c[3])
        : "r"(a[0]), "r"(a[1]), "r"(a[2]), "r"(a[3]), "r"(b[0]), "r"(b[1]));
}
__device__ __forceinline__ void ldsm4(uint32_t addr, uint32_t* r) {
    asm volatile("ldmatrix.sync.aligned.m8n8.x4.shared.b16 {%0,%1,%2,%3}, [%4];"
                 : "=r"(r[0]), "=r"(r[1]), "=r"(r[2]), "=r"(r[3]) : "r"(addr));
}
#define CP16(dst, src) asm volatile("cp.async.cg.shared.global [%0], [%1], 16;" :: "r"(dst), "l"(src))
#define CPCOMMIT()     asm volatile("cp.async.commit_group;" ::: "memory")
#define CPWAIT0()      asm volatile("cp.async.wait_group 0;" ::: "memory")

__device__ __forceinline__ void split_fp16(float v, fp16& hi, fp16& lo) {
    hi = __float2half(v);
    lo = __float2half(v - __half2float(hi));
}

// ---------------- init ----------------
__global__ void k_zero() {
    int i = blockIdx.x * 1024 + threadIdx.x;   // 512x1024 = Bn*Dd
    g_hnT[i] = 0.0f;
    g_hh[i] = __float2half(0.0f);
    g_hl[i] = __float2half(0.0f);
    if (i < 8 * 32) g_barG[i] = 0u;
}

__global__ void k_wconv(const float* __restrict__ W, fp16* __restrict__ Wo) {
    size_t i = (size_t)blockIdx.x * 512 + threadIdx.x;
    Wo[i] = __float2half(W[i]);
}

// ---------------- embeddings: 1024 blocks x 128 rows, weights staged once ----------------
__global__ __launch_bounds__(256) void k_embed(
    const float* __restrict__ ext, const float* __restrict__ obs,
    const float* __restrict__ Wu, const float* __restrict__ bu,
    const float* __restrict__ Wx, const float* __restrict__ bx)
{
    __shared__ float sWu[INU * Hd];    // 32 KB  (k-major: sWu[k*256+col])
    __shared__ float sWx[OUTd * Hd];   // 16 KB
    __shared__ float sIn[128 * INU];   // 16 KB
    __shared__ float sOb[128 * OUTd];  //  8 KB
    const int row0 = blockIdx.x * 128;
    const int tid = threadIdx.x;
    #pragma unroll 4
    for (int i = tid; i < INU * Hd; i += 256) sWu[i] = Wu[i];
    #pragma unroll 4
    for (int i = tid; i < OUTd * Hd; i += 256) sWx[i] = Wx[i];
    #pragma unroll 4
    for (int i = tid; i < 128 * INU; i += 256) {
        int r = i >> 5, k = i & 31;
        sIn[i] = ext[(size_t)(row0 + r) * (INU + 1) + k];
    }
    #pragma unroll 4
    for (int i = tid; i < 128 * OUTd; i += 256) {
        int r = i >> 4, k = i & 15;
        sOb[i] = obs[(size_t)(row0 + r) * OUTd + k];
    }
    __syncthreads();
    const float bu_t = bu[tid];
    const float bx_t = bx[tid];
    for (int r = 0; r < 128; r++) {
        float au = bu_t;
        #pragma unroll
        for (int k = 0; k < INU; k++) au += sIn[r * INU + k] * sWu[k * Hd + tid];
        float ax = bx_t;
        #pragma unroll
        for (int k = 0; k < OUTd; k++) ax += sOb[r * OUTd + k] * sWx[k * Hd + tid];
        size_t base = (size_t)(row0 + r) * Dd;
        g_Xh[base + tid]      = __float2half(tanhf(au));
        g_Xh[base + Hd + tid] = __float2half(tanhf(ax));
    }
}

// ---------------- group barrier (16 blocks sharing mg) ----------------
__device__ __forceinline__ void gbarg(unsigned* ctr, unsigned target) {
    __syncthreads();
    if (threadIdx.x == 0) {
        __threadfence();
        atomicAdd(ctr, 1u);
        while (*((volatile unsigned*)ctr) < target) { }
        __threadfence();
    }
    __syncthreads();
}

// ---------------- W loader: 3 regions, 1024B/row, 16B-slot XOR swizzle ----------------
__device__ void load_Wsw(const fp16* __restrict__ W, int d0, char* sW, int tid) {
    #pragma unroll 4
    for (int it = 0; it < 24; it++) {
        int flat = tid + it * 256;            // uint4 index, 0..6143
        int g = flat >> 11;                   // region 0..2 (gate)
        int rem = flat & 2047;
        int n    = rem >> 6;                  // row 0..31
        int slot = rem & 63;                  // 16B slot (8 fp16)
        uint4 v = *(const uint4*)(W + (size_t)(g * Dd + d0 + n) * Dd + slot * 8);
        *(uint4*)(sW + g * W_REGION + n * 1024 + ((slot ^ (n & 7)) << 4)) = v;
    }
}

// ---------------- GEMM: C[128m x 96n] = A[128,512] @ Wslice^T ----------------
// NS=2: fp16 2-term split (Ah+Al); NS=1: single fp16 (Ah only).
// 64k chunks (two 32k sub-chunks in the proven swizzle layout), double buffered.
template<int NS>
__device__ __forceinline__ void gemm_tile(
    const fp16* __restrict__ Ah, const fp16* __restrict__ Al,
    uint32_t sAu, float acc[3][2][2][4], int tid,
    uint32_t aBase, uint32_t aSlotL, uint32_t aSw,
    uint32_t bBase, uint32_t bKh, uint32_t bSw)
{
    const uint32_t BUFSZ = NS * 16384u;
    #pragma unroll
    for (int g = 0; g < 3; g++)
        #pragma unroll
        for (int i2 = 0; i2 < 2; i2++)
            #pragma unroll
            for (int j2 = 0; j2 < 2; j2++)
                #pragma unroll
                for (int e = 0; e < 4; e++) acc[g][i2][j2][e] = 0.0f;

    // per-thread fill slots (4*NS x 16B per buffer)
    uint32_t fd[4 * NS]; const fp16* fs[4 * NS];
    #pragma unroll
    for (int i = 0; i < 4 * NS; i++) {
        int flat = tid + i * 256;                 // 0..1024*NS-1
        int slot = flat & 3;
        int m = (flat >> 2) & 127;
        int s = (NS == 2) ? ((flat >> 9) & 1) : 0;
        int sub = flat >> ((NS == 2) ? 10 : 9);
        fd[i] = sAu + (uint32_t)sub * (NS * 8192u) + (uint32_t)s * 8192u + (uint32_t)m * 64u
                + ((uint32_t)(slot ^ ((m >> 1) & 3)) << 4);
        fs[i] = (s ? Al : Ah) + (size_t)m * Dd + sub * 32 + slot * 8;
    }
    #pragma unroll
    for (int i = 0; i < 4 * NS; i++) CP16(fd[i], fs[i]);
    CPCOMMIT();

    for (int c = 0; c < 8; c++) {                 // 8 chunks x 64 k
        CPWAIT0();
        __syncthreads();
        if (c < 7) {
            uint32_t nb = ((uint32_t)(c + 1) & 1u) * BUFSZ;
            #pragma unroll
            for (int i = 0; i < 4 * NS; i++) CP16(fd[i] + nb, fs[i] + (c + 1) * 64);
            CPCOMMIT();
        }
        uint32_t ab = aBase + ((uint32_t)(c & 1)) * BUFSZ;
        #pragma unroll
        for (int sub = 0; sub < 2; sub++) {
            uint32_t absub = ab + (uint32_t)sub * (NS * 8192u);
            #pragma unroll
            for (int ks8 = 0; ks8 <= 2; ks8 += 2) {
                uint32_t afr[2][NS][4];
                #pragma unroll
                for (int i2 = 0; i2 < 2; i2++)
                    #pragma unroll
                    for (int s = 0; s < NS; s++)
                        ldsm4(absub + s * 8192u + i2 * 1024u + (((aSlotL + ks8) ^ aSw) << 4), afr[i2][s]);
                uint32_t bfr[3][4];
                uint32_t bslot = (uint32_t)(c * 8 + sub * 4 + ks8) + bKh;
                #pragma unroll
                for (int g = 0; g < 3; g++)
                    ldsm4(bBase + g * W_REGION + ((bslot ^ bSw) << 4), bfr[g]);
                #pragma unroll
                for (int g = 0; g < 3; g++)
                    #pragma unroll
                    for (int i2 = 0; i2 < 2; i2++)
                        #pragma unroll
                        for (int j2 = 0; j2 < 2; j2++) {
                            mma16816(acc[g][i2][j2], afr[i2][0], &bfr[g][j2 * 2]);
                            if (NS == 2)
                                mma16816(acc[g][i2][j2], afr[i2][1], &bfr[g][j2 * 2]);
                        }
            }
        }
    }
}

// ---------------- THE persistent kernel ----------------
__global__ void __launch_bounds__(256, 1) k_persist(
    const float* __restrict__ ext,
    const float* __restrict__ bih, const float* __restrict__ bhh,
    const float* __restrict__ W1, const float* __restrict__ b1,
    const float* __restrict__ W2, const float* __restrict__ b2)
{
    extern __shared__ char smem[];
    uint32_t sWu_ = smem_to_u32(smem);
    uint32_t sAu = sWu_ + OFF_SA;
    float* s_h  = (float*)(smem + OFF_SA);            // [8][260]   (overlay on sA)
    float* s_zp = (float*)(smem + OFF_SA + 8320);     // [2][8][132] partials -> z in [0]
    float* s_c  = (float*)(smem + OFF_SA + 16768);    // [8][130]
    float* s_dt = (float*)(smem + OFF_SA + 20928);    // [8]

    const int tid = threadIdx.x;
    const int wid = tid >> 5, lane = tid & 31;
    const int bid = blockIdx.x;
    const int dtile = bid & 15, mg = bid >> 4;
    const int d0 = dtile * 32;
    const int m0ode = bid * 8;
    const int warp_m = wid >> 1, warp_n = wid & 1;
    const int q = lane >> 2, tp = lane & 3;
    unsigned* gctr = &g_barG[mg * 32];
    unsigned bar_t = 0;

    // ldmatrix per-lane constants
    const int aRow = warp_m * 32 + (lane & 7) + ((lane >> 3) & 1) * 8;
    const uint32_t aBase = sAu + (uint32_t)aRow * 64;
    const uint32_t aSlotL = (uint32_t)(lane >> 4);
    const uint32_t aSw = (uint32_t)((aRow >> 1) & 3);
    const int bRowN = warp_n * 16 + (lane & 7) + ((lane >> 4) & 1) * 8;
    const uint32_t bBase = sWu_ + (uint32_t)bRowN * 1024;
    const uint32_t bKh = (uint32_t)((lane >> 3) & 1);
    const uint32_t bSw = (uint32_t)(bRowN & 7);

    float acc[3][2][2][4];

    // per-thread bias values (d depends only on j2, eo)
    float bI[3][2][2], bH[3][2][2];
    #pragma unroll
    for (int g = 0; g < 3; g++)
        #pragma unroll
        for (int j2 = 0; j2 < 2; j2++)
            #pragma unroll
            for (int eo = 0; eo < 2; eo++) {
                int d = d0 + warp_n * 16 + j2 * 8 + tp * 2 + eo;
                bI[g][j2][eo] = bih[g * Dd + d];
                bH[g][j2][eo] = bhh[g * Dd + d];
            }

    // ======== Phase 1: gi = X @ W_ih^T + b_ih (single fp16 term) ========
    load_Wsw(g_Wih, d0, smem, tid);
    __syncthreads();
    for (int t = 0; t < 127; t++) {
        const fp16* Ah = g_Xh + ((size_t)t * Bn + mg * 128) * Dd;
        gemm_tile<1>(Ah, Ah, sAu, acc, tid, aBase, aSlotL, aSw, bBase, bKh, bSw);
        float* giT = g_giT + (size_t)t * G3 * Bn;
        #pragma unroll
        for (int i2 = 0; i2 < 2; i2++)
            #pragma unroll
            for (int j2 = 0; j2 < 2; j2++)
                #pragma unroll
                for (int e = 0; e < 4; e++) {
                    int b = mg * 128 + warp_m * 32 + i2 * 16 + q + (e >> 1) * 8;
                    int d = d0 + warp_n * 16 + j2 * 8 + tp * 2 + (e & 1);
                    #pragma unroll
                    for (int g = 0; g < 3; g++)
                        giT[(size_t)(g * Dd + d) * Bn + b] = acc[g][i2][j2][e] + bI[g][j2][e & 1];
                }
    }

    // ======== Phase 2: recurrent loop (group-local synchronization only) ========
    __syncthreads();                      // all warps done reading W_ih smem
    load_Wsw(g_Whh, d0, smem, tid);
    __syncthreads();

    for (int t = 0; t < 127; t++) {
        gemm_tile<2>(g_hh + (size_t)mg * 128 * Dd, g_hl + (size_t)mg * 128 * Dd,
                     sAu, acc, tid, aBase, aSlotL, aSw, bBase, bKh, bSw);
        // fused GRU gates epilogue -> g_tmpT
        const float* giT = g_giT + (size_t)t * G3 * Bn;
        const float* hpT = g_hnT + (size_t)t * Dd * Bn;
        #pragma unroll
        for (int i2 = 0; i2 < 2; i2++)
            #pragma unroll
            for (int j2 = 0; j2 < 2; j2++)
                #pragma unroll
                for (int e = 0; e < 4; e++) {
                    int b = mg * 128 + warp_m * 32 + i2 * 16 + q + (e >> 1) * 8;
                    int d = d0 + warp_n * 16 + j2 * 8 + tp * 2 + (e & 1);
                    float gR = acc[0][i2][j2][e] + bH[0][j2][e & 1];
                    float gZ = acc[1][i2][j2][e] + bH[1][j2][e & 1];
                    float gN = acc[2][i2][j2][e] + bH[2][j2][e & 1];
                    float giR = __ldcg(&giT[(size_t)d * Bn + b]);
                    float giZ = __ldcg(&giT[(size_t)(Dd + d) * Bn + b]);
                    float giN = __ldcg(&giT[(size_t)(2 * Dd + d) * Bn + b]);
                    float r = 1.0f / (1.0f + __expf(-(giR + gR)));
                    float z = 1.0f / (1.0f + __expf(-(giZ + gZ)));
                    float nn = tanhf(giN + r * gN);
                    float hp = __ldcg(&hpT[(size_t)d * Bn + b]);
                    g_tmpT[(size_t)d * Bn + b] = (1.0f - z) * nn + z * hp;
                }
        bar_t += 16; gbarg(gctr, bar_t);   // group's epilogues done

        // ---- ODE MLP + Euler for rows m0ode..m0ode+7 ----
        #pragma unroll
        for (int i = 0; i < 8; i++) {
            int idx = tid + i * 256;
            int r = idx & 7, cc = idx >> 3;           // cc 0..255
            s_h[r * 260 + cc] = __ldcg(&g_tmpT[(size_t)cc * Bn + m0ode + r]);
        }
        if (tid < 8) s_dt[tid] = ext[((size_t)t * Bn + m0ode + tid) * (INU + 1) + INU];
        __syncthreads();
        {   // z = tanh(h @ W1 + b1), k-split across warp halves (W1 read exactly once)
            int col = tid & 127, half = tid >> 7;
            float a[8];
            #pragma unroll
            for (int r = 0; r < 8; r++) a[r] = 0.0f;
            const int kb = half * 128;
            #pragma unroll 4
            for (int k = 0; k < 128; k++) {
                float w = W1[(kb + k) * ODEH + col];
                #pragma unroll
                for (int r = 0; r < 8; r++) a[r] += s_h[r * 260 + kb + k] * w;
            }
            #pragma unroll
            for (int r = 0; r < 8; r++) s_zp[half * 1056 + r * 132 + col] = a[r];
        }
        __syncthreads();
        #pragma unroll
        for (int i = 0; i < 4; i++) {                 // combine halves + tanh (into s_zp[0])
            int idx = tid + i * 256;
            int r = idx >> 7, c = idx & 127;
            s_zp[r * 132 + c] = tanhf(s_zp[r * 132 + c] + s_zp[1056 + r * 132 + c] + b1[c]);
        }
        __syncthreads();
        float hnew[8];
        {   // f = z @ W2 + b2 ; hnew = h + dt*f ; write h splits (m-major)
            int col = tid;
            float f[8];
            float bb = b2[col];
            #pragma unroll
            for (int r = 0; r < 8; r++) f[r] = bb;
            #pragma unroll 4
            for (int k = 0; k < ODEH; k++) {
                float w = W2[k * Hd + col];
                #pragma unroll
                for (int r = 0; r < 8; r++) f[r] += s_zp[r * 132 + k] * w;
            }
            #pragma unroll
            for (int r = 0; r < 8; r++) {
                hnew[r] = s_h[r * 260 + col] + s_dt[r] * f[r];
                fp16 hi, lo; split_fp16(hnew[r], hi, lo);
                g_hh[(size_t)(m0ode + r) * Dd + col] = hi;
                g_hl[(size_t)(m0ode + r) * Dd + col] = lo;
            }
        }
        __syncthreads();
        {   int col = tid;
            #pragma unroll
            for (int r = 0; r < 8; r++) s_h[r * 260 + col] = hnew[r];
        }
        __syncthreads();
        float* hnT1 = g_hnT + (size_t)(t + 1) * Dd * Bn;
        #pragma unroll
        for (int i = 0; i < 8; i++) {
            int idx = tid + i * 256;
            int r = idx & 7, cc = idx >> 3;
            hnT1[(size_t)cc * Bn + m0ode + r] = s_h[r * 260 + cc];
        }
        #pragma unroll
        for (int ch = 0; ch < 2; ch++) {              // c passthrough + splits
            int cbase = Hd + ch * 128;
            #pragma unroll
            for (int i = 0; i < 4; i++) {
                int idx = tid + i * 256;
                int r = idx & 7, cl = idx >> 3;
                float x = __ldcg(&g_tmpT[(size_t)(cbase + cl) * Bn + m0ode + r]);
                hnT1[(size_t)(cbase + cl) * Bn + m0ode + r] = x;
                s_c[r * 130 + cl] = x;
            }
            __syncthreads();
            #pragma unroll
            for (int i = 0; i < 4; i++) {
                int idx = tid + i * 256;
                int r = idx >> 7, cl = idx & 127;
                float x = s_c[r * 130 + cl];
                fp16 hi, lo; split_fp16(x, hi, lo);
                g_hh[(size_t)(m0ode + r) * Dd + cbase + cl] = hi;
                g_hl[(size_t)(m0ode + r) * Dd + cbase + cl] = lo;
            }
            __syncthreads();
        }
        bar_t += 16; gbarg(gctr, bar_t);   // group's ODE done -> next GEMM may read g_hh
    }
}

// ---------------- output projection ----------------
__global__ __launch_bounds__(256) void k_out(
    const float* __restrict__ WLy, const float* __restrict__ bLy,
    float* __restrict__ out)
{
    __shared__ float s_w[Dd * OUTd];   // 32 KB
    int t = blockIdx.x >> 3;
    int b0 = (blockIdx.x & 7) * 128;
    int tid = threadIdx.x;
    #pragma unroll
    for (int i = 0; i < 32; i++) s_w[tid + i * 256] = WLy[tid + i * 256];
    __syncthreads();
    int b = b0 + (tid >> 1);
    int oh = (tid & 1) * 8;
    const float* hp = g_hnT + (size_t)t * Dd * Bn;
    float a[8];
    #pragma unroll
    for (int j = 0; j < 8; j++) a[j] = bLy[oh + j];
    #pragma unroll 4
    for (int k = 0; k < Dd; k++) {
        float v = __ldg(&hp[(size_t)k * Bn + b]);
        #pragma unroll
        for (int j = 0; j < 8; j++) a[j] += v * s_w[k * OUTd + oh + j];
    }
    float* op = out + ((size_t)t * Bn + b) * OUTd + oh;
    *(float4*)(op)     = make_float4(a[0], a[1], a[2], a[3]);
    *(float4*)(op + 4) = make_float4(a[4], a[5], a[6], a[7]);
}

// ---------------- launch ----------------
extern "C" void kernel_launch(void* const* d_in, const int* in_sizes, int n_in,
                              void* d_out, int out_size)
{
    const float* ext = (const float*)d_in[0];
    const float* obs = (const float*)d_in[1];
    const float* Wu  = (const float*)d_in[2];
    const float* bu  = (const float*)d_in[3];
    const float* Wx  = (const float*)d_in[4];
    const float* bx  = (const float*)d_in[5];
    const float* Wih = (const float*)d_in[6];
    const float* Whh = (const float*)d_in[7];
    const float* bih = (const float*)d_in[8];
    const float* bhh = (const float*)d_in[9];
    const float* W1  = (const float*)d_in[10];
    const float* b1  = (const float*)d_in[11];
    const float* W2  = (const float*)d_in[12];
    const float* b2  = (const float*)d_in[13];
    const float* WLy = (const float*)d_in[14];
    const float* bLy = (const float*)d_in[15];
    float* out = (float*)d_out;

    fp16 *p_Wih, *p_Whh;
    cudaGetSymbolAddress((void**)&p_Wih, g_Wih);
    cudaGetSymbolAddress((void**)&p_Whh, g_Whh);

    cudaFuncSetAttribute(k_persist, cudaFuncAttributeMaxDynamicSharedMemorySize, SMEM_TOTAL);

    k_zero<<<512, 1024>>>();
    k_wconv<<<G3, 512>>>(Wih, p_Wih);
    k_wconv<<<G3, 512>>>(Whh, p_Whh);
    k_embed<<<ROWS / 128, 256>>>(ext, obs, Wu, bu, Wx, bx);

    k_persist<<<NBLK, 256, SMEM_TOTAL>>>(ext, bih, bhh, W1, b1, W2, b2);

    k_out<<<Ln * 8, 256>>>(WLy, bLy, out);
}

// round 14
// speedup vs baseline: 3.0374x; 1.0492x over previous
#include <cuda_runtime.h>
#include <cuda_fp16.h>
#include <cstdint>

// Problem constants
#define Ln   128
#define Bn   1024
#define Hd   256
#define Dd   512
#define G3   1536
#define ODEH 128
#define INU  32
#define OUTd 16
#define ROWS (Ln * Bn)  // 131072
#define NBLK 128        // persistent grid, 1 CTA/SM via smem

typedef __half fp16;

// ---------------- scratch (device globals; no allocs allowed) ----------------
__device__ fp16  g_Xh [(size_t)ROWS * Dd];     // embeddings fp16 (m-major)
__device__ float g_giT[(size_t)Ln * G3 * Bn];  // gi TRANSPOSED [t][gate*512+d][b]
__device__ float g_hnT[(size_t)Ln * Dd * Bn];  // hn history TRANSPOSED [t][d][b]
__device__ float g_tmpT[(size_t)Dd * Bn];      // GRU out TRANSPOSED [d][b]
__device__ fp16  g_hh [Bn * Dd], g_hl[Bn * Dd];  // current h splits (m-major)
__device__ fp16  g_Wih[G3 * Dd];               // W_ih fp16
__device__ fp16  g_Whh[G3 * Dd];               // W_hh fp16
__device__ unsigned g_barG[16 * 32];           // per-mg group barrier counters (128B apart)

// ---------------- smem map ----------------
// W: 3 regions (one per gate), each 64 rows x 512 k fp16, 1024B/row,
//    16B-slot XOR swizzle (slot ^ (n&7)) -> conflict-free ldmatrix.
#define W_REGION 65536
#define SW_BYTES (3 * W_REGION)           // 196608
#define OFF_SA   SW_BYTES
// A double buffer: 2 x (NS * 8192); max NS=2 -> 32KB
#define SMEM_TOTAL (SW_BYTES + 32768)     // 229376

// ---------------- asm helpers ----------------
__device__ __forceinline__ uint32_t smem_to_u32(const void* p) {
    uint32_t a;
    asm("{ .reg .u64 t; cvta.to.shared.u64 t, %1; cvt.u32.u64 %0, t; }" : "=r"(a) : "l"(p));
    return a;
}
__device__ __forceinline__ void mma16816(float* c, const unsigned* a, const unsigned* b) {
    asm volatile(
        "mma.sync.aligned.m16n8k16.row.col.f32.f16.f16.f32 "
        "{%0,%1,%2,%3}, {%4,%5,%6,%7}, {%8,%9}, {%0,%1,%2,%3};\n"
        : "+f"(c[0]), "+f"(c[1]), "+f"(c[2]), "+f"(c[3])
        : "r"(a[0]), "r"(a[1]), "r"(a[2]), "r"(a[3]), "r"(b[0]), "r"(b[1]));
}
__device__ __forceinline__ void ldsm4(uint32_t addr, uint32_t* r) {
    asm volatile("ldmatrix.sync.aligned.m8n8.x4.shared.b16 {%0,%1,%2,%3}, [%4];"
                 : "=r"(r[0]), "=r"(r[1]), "=r"(r[2]), "=r"(r[3]) : "r"(addr));
}
#define CP16(dst, src) asm volatile("cp.async.cg.shared.global [%0], [%1], 16;" :: "r"(dst), "l"(src))
#define CPCOMMIT()     asm volatile("cp.async.commit_group;" ::: "memory")
#define CPWAIT0()      asm volatile("cp.async.wait_group 0;" ::: "memory")

__device__ __forceinline__ void split_fp16(float v, fp16& hi, fp16& lo) {
    hi = __float2half(v);
    lo = __float2half(v - __half2float(hi));
}

// ---------------- init ----------------
__global__ void k_zero() {
    int i = blockIdx.x * 1024 + threadIdx.x;   // 512x1024 = Bn*Dd
    g_hnT[i] = 0.0f;
    g_hh[i] = __float2half(0.0f);
    g_hl[i] = __float2half(0.0f);
    if (i < 16 * 32) g_barG[i] = 0u;
}

__global__ void k_wconv(const float* __restrict__ W, fp16* __restrict__ Wo) {
    size_t i = (size_t)blockIdx.x * 512 + threadIdx.x;
    Wo[i] = __float2half(W[i]);
}

// ---------------- embeddings: 1024 blocks x 128 rows, weights staged once ----------------
__global__ __launch_bounds__(256) void k_embed(
    const float* __restrict__ ext, const float* __restrict__ obs,
    const float* __restrict__ Wu, const float* __restrict__ bu,
    const float* __restrict__ Wx, const float* __restrict__ bx)
{
    __shared__ float sWu[INU * Hd];    // 32 KB  (k-major: sWu[k*256+col])
    __shared__ float sWx[OUTd * Hd];   // 16 KB
    __shared__ float sIn[128 * INU];   // 16 KB
    __shared__ float sOb[128 * OUTd];  //  8 KB
    const int row0 = blockIdx.x * 128;
    const int tid = threadIdx.x;
    #pragma unroll 4
    for (int i = tid; i < INU * Hd; i += 256) sWu[i] = Wu[i];
    #pragma unroll 4
    for (int i = tid; i < OUTd * Hd; i += 256) sWx[i] = Wx[i];
    #pragma unroll 4
    for (int i = tid; i < 128 * INU; i += 256) {
        int r = i >> 5, k = i & 31;
        sIn[i] = ext[(size_t)(row0 + r) * (INU + 1) + k];
    }
    #pragma unroll 4
    for (int i = tid; i < 128 * OUTd; i += 256) {
        int r = i >> 4, k = i & 15;
        sOb[i] = obs[(size_t)(row0 + r) * OUTd + k];
    }
    __syncthreads();
    const float bu_t = bu[tid];
    const float bx_t = bx[tid];
    for (int r = 0; r < 128; r++) {
        float au = bu_t;
        #pragma unroll
        for (int k = 0; k < INU; k++) au += sIn[r * INU + k] * sWu[k * Hd + tid];
        float ax = bx_t;
        #pragma unroll
        for (int k = 0; k < OUTd; k++) ax += sOb[r * OUTd + k] * sWx[k * Hd + tid];
        size_t base = (size_t)(row0 + r) * Dd;
        g_Xh[base + tid]      = __float2half(tanhf(au));
        g_Xh[base + Hd + tid] = __float2half(tanhf(ax));
    }
}

// ---------------- group barrier (8 blocks sharing mg) ----------------
__device__ __forceinline__ void gbarg(unsigned* ctr, unsigned target) {
    __syncthreads();
    if (threadIdx.x == 0) {
        __threadfence();
        atomicAdd(ctr, 1u);
        while (*((volatile unsigned*)ctr) < target) { }
        __threadfence();
    }
    __syncthreads();
}

// ---------------- W loader: 3 regions, 64 rows, 1024B/row, 16B-slot XOR swizzle ----------------
__device__ void load_Wsw(const fp16* __restrict__ W, int d0, char* sW, int tid) {
    #pragma unroll 4
    for (int it = 0; it < 48; it++) {
        int flat = tid + it * 256;            // uint4 index, 0..12287
        int g = flat >> 12;                   // region 0..2 (gate)
        int rem = flat & 4095;
        int n    = rem >> 6;                  // row 0..63
        int slot = rem & 63;                  // 16B slot (8 fp16)
        uint4 v = *(const uint4*)(W + (size_t)(g * Dd + d0 + n) * Dd + slot * 8);
        *(uint4*)(sW + g * W_REGION + n * 1024 + ((slot ^ (n & 7)) << 4)) = v;
    }
}

// ---------------- GEMM: C[64m x 192n] = A[64,512] @ Wslice^T ----------------
// NS=2: fp16 2-term split (Ah+Al); NS=1: single fp16 (Ah only).
// 64k chunks (two 32k sub-chunks), double buffered.
template<int NS>
__device__ __forceinline__ void gemm_tile(
    const fp16* __restrict__ Ah, const fp16* __restrict__ Al,
    uint32_t sAu, float acc[3][2][2][4], int tid,
    uint32_t aBase, uint32_t aSlotL, uint32_t aSw,
    uint32_t bBase, uint32_t bKh, uint32_t bSw)
{
    const uint32_t BUFSZ = NS * 8192u;
    #pragma unroll
    for (int g = 0; g < 3; g++)
        #pragma unroll
        for (int i2 = 0; i2 < 2; i2++)
            #pragma unroll
            for (int j2 = 0; j2 < 2; j2++)
                #pragma unroll
                for (int e = 0; e < 4; e++) acc[g][i2][j2][e] = 0.0f;

    // per-thread fill slots (2*NS x 16B per buffer)
    // buffer layout: [sub(2)][s(NS)][m(64)][slot(4) swizzled]
    uint32_t fd[2 * NS]; const fp16* fs[2 * NS];
    #pragma unroll
    for (int i = 0; i < 2 * NS; i++) {
        int flat = tid + i * 256;                 // 0..512*NS-1
        int slot = flat & 3;
        int m = (flat >> 2) & 63;
        int s = (NS == 2) ? ((flat >> 8) & 1) : 0;
        int sub = flat >> ((NS == 2) ? 9 : 8);
        fd[i] = sAu + (uint32_t)sub * (NS * 4096u) + (uint32_t)s * 4096u + (uint32_t)m * 64u
                + ((uint32_t)(slot ^ ((m >> 1) & 3)) << 4);
        fs[i] = (s ? Al : Ah) + (size_t)m * Dd + sub * 32 + slot * 8;
    }
    #pragma unroll
    for (int i = 0; i < 2 * NS; i++) CP16(fd[i], fs[i]);
    CPCOMMIT();

    for (int c = 0; c < 8; c++) {                 // 8 chunks x 64 k
        CPWAIT0();
        __syncthreads();
        if (c < 7) {
            uint32_t nb = ((uint32_t)(c + 1) & 1u) * BUFSZ;
            #pragma unroll
            for (int i = 0; i < 2 * NS; i++) CP16(fd[i] + nb, fs[i] + (c + 1) * 64);
            CPCOMMIT();
        }
        uint32_t ab = aBase + ((uint32_t)(c & 1)) * BUFSZ;
        #pragma unroll
        for (int sub = 0; sub < 2; sub++) {
            uint32_t absub = ab + (uint32_t)sub * (NS * 4096u);
            #pragma unroll
            for (int ks8 = 0; ks8 <= 2; ks8 += 2) {
                uint32_t afr[2][NS][4];
                #pragma unroll
                for (int i2 = 0; i2 < 2; i2++)
                    #pragma unroll
                    for (int s = 0; s < NS; s++)
                        ldsm4(absub + s * 4096u + i2 * 1024u + (((aSlotL + ks8) ^ aSw) << 4), afr[i2][s]);
                uint32_t bfr[3][4];
                uint32_t bslot = (uint32_t)(c * 8 + sub * 4 + ks8) + bKh;
                #pragma unroll
                for (int g = 0; g < 3; g++)
                    ldsm4(bBase + g * W_REGION + ((bslot ^ bSw) << 4), bfr[g]);
                #pragma unroll
                for (int g = 0; g < 3; g++)
                    #pragma unroll
                    for (int i2 = 0; i2 < 2; i2++)
                        #pragma unroll
                        for (int j2 = 0; j2 < 2; j2++) {
                            mma16816(acc[g][i2][j2], afr[i2][0], &bfr[g][j2 * 2]);
                            if (NS == 2)
                                mma16816(acc[g][i2][j2], afr[i2][1], &bfr[g][j2 * 2]);
                        }
            }
        }
    }
}

// ---------------- THE persistent kernel ----------------
__global__ void __launch_bounds__(256, 1) k_persist(
    const float* __restrict__ ext,
    const float* __restrict__ bih, const float* __restrict__ bhh,
    const float* __restrict__ W1, const float* __restrict__ b1,
    const float* __restrict__ W2, const float* __restrict__ b2)
{
    extern __shared__ char smem[];
    uint32_t sWu_ = smem_to_u32(smem);
    uint32_t sAu = sWu_ + OFF_SA;
    float* s_h  = (float*)(smem + OFF_SA);            // [8][260]   (overlay on sA)
    float* s_zp = (float*)(smem + OFF_SA + 8320);     // [2][8][132] partials -> z in [0]
    float* s_c  = (float*)(smem + OFF_SA + 16768);    // [8][130]
    float* s_dt = (float*)(smem + OFF_SA + 20928);    // [8]

    const int tid = threadIdx.x;
    const int wid = tid >> 5, lane = tid & 31;
    const int bid = blockIdx.x;
    const int dtile = bid & 7, mg = bid >> 3;         // 8 d-tiles x 64, 16 m-groups x 64
    const int d0 = dtile * 64;
    const int m0ode = bid * 8;
    const int warp_m = wid >> 2, warp_n = wid & 3;    // 2 x 4 warp grid
    const int q = lane >> 2, tp = lane & 3;
    unsigned* gctr = &g_barG[mg * 32];
    unsigned bar_t = 0;

    // ldmatrix per-lane constants
    const int aRow = warp_m * 32 + (lane & 7) + ((lane >> 3) & 1) * 8;
    const uint32_t aBase = sAu + (uint32_t)aRow * 64;
    const uint32_t aSlotL = (uint32_t)(lane >> 4);
    const uint32_t aSw = (uint32_t)((aRow >> 1) & 3);
    const int bRowN = warp_n * 16 + (lane & 7) + ((lane >> 4) & 1) * 8;
    const uint32_t bBase = sWu_ + (uint32_t)bRowN * 1024;
    const uint32_t bKh = (uint32_t)((lane >> 3) & 1);
    const uint32_t bSw = (uint32_t)(bRowN & 7);

    float acc[3][2][2][4];

    // per-thread bias values (d depends only on j2, eo)
    float bI[3][2][2], bH[3][2][2];
    #pragma unroll
    for (int g = 0; g < 3; g++)
        #pragma unroll
        for (int j2 = 0; j2 < 2; j2++)
            #pragma unroll
            for (int eo = 0; eo < 2; eo++) {
                int d = d0 + warp_n * 16 + j2 * 8 + tp * 2 + eo;
                bI[g][j2][eo] = bih[g * Dd + d];
                bH[g][j2][eo] = bhh[g * Dd + d];
            }

    // ======== Phase 1: gi = X @ W_ih^T + b_ih (single fp16 term) ========
    load_Wsw(g_Wih, d0, smem, tid);
    __syncthreads();
    for (int t = 0; t < 127; t++) {
        const fp16* Ah = g_Xh + ((size_t)t * Bn + mg * 64) * Dd;
        gemm_tile<1>(Ah, Ah, sAu, acc, tid, aBase, aSlotL, aSw, bBase, bKh, bSw);
        float* giT = g_giT + (size_t)t * G3 * Bn;
        #pragma unroll
        for (int i2 = 0; i2 < 2; i2++)
            #pragma unroll
            for (int j2 = 0; j2 < 2; j2++)
                #pragma unroll
                for (int e = 0; e < 4; e++) {
                    int b = mg * 64 + warp_m * 32 + i2 * 16 + q + (e >> 1) * 8;
                    int d = d0 + warp_n * 16 + j2 * 8 + tp * 2 + (e & 1);
                    #pragma unroll
                    for (int g = 0; g < 3; g++)
                        giT[(size_t)(g * Dd + d) * Bn + b] = acc[g][i2][j2][e] + bI[g][j2][e & 1];
                }
    }

    // ======== Phase 2: recurrent loop (group-local synchronization only) ========
    __syncthreads();                      // all warps done reading W_ih smem
    load_Wsw(g_Whh, d0, smem, tid);
    __syncthreads();

    for (int t = 0; t < 127; t++) {
        gemm_tile<2>(g_hh + (size_t)mg * 64 * Dd, g_hl + (size_t)mg * 64 * Dd,
                     sAu, acc, tid, aBase, aSlotL, aSw, bBase, bKh, bSw);
        // fused GRU gates epilogue -> g_tmpT
        const float* giT = g_giT + (size_t)t * G3 * Bn;
        const float* hpT = g_hnT + (size_t)t * Dd * Bn;
        #pragma unroll
        for (int i2 = 0; i2 < 2; i2++)
            #pragma unroll
            for (int j2 = 0; j2 < 2; j2++)
                #pragma unroll
                for (int e = 0; e < 4; e++) {
                    int b = mg * 64 + warp_m * 32 + i2 * 16 + q + (e >> 1) * 8;
                    int d = d0 + warp_n * 16 + j2 * 8 + tp * 2 + (e & 1);
                    float gR = acc[0][i2][j2][e] + bH[0][j2][e & 1];
                    float gZ = acc[1][i2][j2][e] + bH[1][j2][e & 1];
                    float gN = acc[2][i2][j2][e] + bH[2][j2][e & 1];
                    float giR = __ldcg(&giT[(size_t)d * Bn + b]);
                    float giZ = __ldcg(&giT[(size_t)(Dd + d) * Bn + b]);
                    float giN = __ldcg(&giT[(size_t)(2 * Dd + d) * Bn + b]);
                    float r = 1.0f / (1.0f + __expf(-(giR + gR)));
                    float z = 1.0f / (1.0f + __expf(-(giZ + gZ)));
                    float nn = tanhf(giN + r * gN);
                    float hp = __ldcg(&hpT[(size_t)d * Bn + b]);
                    g_tmpT[(size_t)d * Bn + b] = (1.0f - z) * nn + z * hp;
                }
        bar_t += 8; gbarg(gctr, bar_t);   // group's epilogues done

        // ---- ODE MLP + Euler for rows m0ode..m0ode+7 ----
        #pragma unroll
        for (int i = 0; i < 8; i++) {
            int idx = tid + i * 256;
            int r = idx & 7, cc = idx >> 3;           // cc 0..255
            s_h[r * 260 + cc] = __ldcg(&g_tmpT[(size_t)cc * Bn + m0ode + r]);
        }
        if (tid < 8) s_dt[tid] = ext[((size_t)t * Bn + m0ode + tid) * (INU + 1) + INU];
        __syncthreads();
        {   // z = tanh(h @ W1 + b1), k-split across warp halves (W1 read exactly once)
            int col = tid & 127, half = tid >> 7;
            float a[8];
            #pragma unroll
            for (int r = 0; r < 8; r++) a[r] = 0.0f;
            const int kb = half * 128;
            #pragma unroll 4
            for (int k = 0; k < 128; k++) {
                float w = W1[(kb + k) * ODEH + col];
                #pragma unroll
                for (int r = 0; r < 8; r++) a[r] += s_h[r * 260 + kb + k] * w;
            }
            #pragma unroll
            for (int r = 0; r < 8; r++) s_zp[half * 1056 + r * 132 + col] = a[r];
        }
        __syncthreads();
        #pragma unroll
        for (int i = 0; i < 4; i++) {                 // combine halves + tanh (into s_zp[0])
            int idx = tid + i * 256;
            int r = idx >> 7, c = idx & 127;
            s_zp[r * 132 + c] = tanhf(s_zp[r * 132 + c] + s_zp[1056 + r * 132 + c] + b1[c]);
        }
        __syncthreads();
        float hnew[8];
        {   // f = z @ W2 + b2 ; hnew = h + dt*f ; write h splits (m-major)
            int col = tid;
            float f[8];
            float bb = b2[col];
            #pragma unroll
            for (int r = 0; r < 8; r++) f[r] = bb;
            #pragma unroll 4
            for (int k = 0; k < ODEH; k++) {
                float w = W2[k * Hd + col];
                #pragma unroll
                for (int r = 0; r < 8; r++) f[r] += s_zp[r * 132 + k] * w;
            }
            #pragma unroll
            for (int r = 0; r < 8; r++) {
                hnew[r] = s_h[r * 260 + col] + s_dt[r] * f[r];
                fp16 hi, lo; split_fp16(hnew[r], hi, lo);
                g_hh[(size_t)(m0ode + r) * Dd + col] = hi;
                g_hl[(size_t)(m0ode + r) * Dd + col] = lo;
            }
        }
        __syncthreads();
        {   int col = tid;
            #pragma unroll
            for (int r = 0; r < 8; r++) s_h[r * 260 + col] = hnew[r];
        }
        __syncthreads();
        float* hnT1 = g_hnT + (size_t)(t + 1) * Dd * Bn;
        #pragma unroll
        for (int i = 0; i < 8; i++) {
            int idx = tid + i * 256;
            int r = idx & 7, cc = idx >> 3;
            hnT1[(size_t)cc * Bn + m0ode + r] = s_h[r * 260 + cc];
        }
        #pragma unroll
        for (int ch = 0; ch < 2; ch++) {              // c passthrough + splits
            int cbase = Hd + ch * 128;
            #pragma unroll
            for (int i = 0; i < 4; i++) {
                int idx = tid + i * 256;
                int r = idx & 7, cl = idx >> 3;
                float x = __ldcg(&g_tmpT[(size_t)(cbase + cl) * Bn + m0ode + r]);
                hnT1[(size_t)(cbase + cl) * Bn + m0ode + r] = x;
                s_c[r * 130 + cl] = x;
            }
            __syncthreads();
            #pragma unroll
            for (int i = 0; i < 4; i++) {
                int idx = tid + i * 256;
                int r = idx >> 7, cl = idx & 127;
                float x = s_c[r * 130 + cl];
                fp16 hi, lo; split_fp16(x, hi, lo);
                g_hh[(size_t)(m0ode + r) * Dd + cbase + cl] = hi;
                g_hl[(size_t)(m0ode + r) * Dd + cbase + cl] = lo;
            }
            __syncthreads();
        }
        bar_t += 8; gbarg(gctr, bar_t);   // group's ODE done -> next GEMM may read g_hh
    }
}

// ---------------- output projection ----------------
__global__ __launch_bounds__(256) void k_out(
    const float* __restrict__ WLy, const float* __restrict__ bLy,
    float* __restrict__ out)
{
    __shared__ float s_w[Dd * OUTd];   // 32 KB
    int t = blockIdx.x >> 3;
    int b0 = (blockIdx.x & 7) * 128;
    int tid = threadIdx.x;
    #pragma unroll
    for (int i = 0; i < 32; i++) s_w[tid + i * 256] = WLy[tid + i * 256];
    __syncthreads();
    int b = b0 + (tid >> 1);
    int oh = (tid & 1) * 8;
    const float* hp = g_hnT + (size_t)t * Dd * Bn;
    float a[8];
    #pragma unroll
    for (int j = 0; j < 8; j++) a[j] = bLy[oh + j];
    #pragma unroll 4
    for (int k = 0; k < Dd; k++) {
        float v = __ldg(&hp[(size_t)k * Bn + b]);
        #pragma unroll
        for (int j = 0; j < 8; j++) a[j] += v * s_w[k * OUTd + oh + j];
    }
    float* op = out + ((size_t)t * Bn + b) * OUTd + oh;
    *(float4*)(op)     = make_float4(a[0], a[1], a[2], a[3]);
    *(float4*)(op + 4) = make_float4(a[4], a[5], a[6], a[7]);
}

// ---------------- launch ----------------
extern "C" void kernel_launch(void* const* d_in, const int* in_sizes, int n_in,
                              void* d_out, int out_size)
{
    const float* ext = (const float*)d_in[0];
    const float* obs = (const float*)d_in[1];
    const float* Wu  = (const float*)d_in[2];
    const float* bu  = (const float*)d_in[3];
    const float* Wx  = (const float*)d_in[4];
    const float* bx  = (const float*)d_in[5];
    const float* Wih = (const float*)d_in[6];
    const float* Whh = (const float*)d_in[7];
    const float* bih = (const float*)d_in[8];
    const float* bhh = (const float*)d_in[9];
    const float* W1  = (const float*)d_in[10];
    const float* b1  = (const float*)d_in[11];
    const float* W2  = (const float*)d_in[12];
    const float* b2  = (const float*)d_in[13];
    const float* WLy = (const float*)d_in[14];
    const float* bLy = (const float*)d_in[15];
    float* out = (float*)d_out;

    fp16 *p_Wih, *p_Whh;
    cudaGetSymbolAddress((void**)&p_Wih, g_Wih);
    cudaGetSymbolAddress((void**)&p_Whh, g_Whh);

    cudaFuncSetAttribute(k_persist, cudaFuncAttributeMaxDynamicSharedMemorySize, SMEM_TOTAL);

    k_zero<<<512, 1024>>>();
    k_wconv<<<G3, 512>>>(Wih, p_Wih);
    k_wconv<<<G3, 512>>>(Whh, p_Whh);
    k_embed<<<ROWS / 128, 256>>>(ext, obs, Wu, bu, Wx, bx);

    k_persist<<<NBLK, 256, SMEM_TOTAL>>>(ext, bih, bhh, W1, b1, W2, b2);

    k_out<<<Ln * 8, 256>>>(WLy, bLy, out);
}

// round 15
// speedup vs baseline: 3.2543x; 1.0714x over previous
#include <cuda_runtime.h>
#include <cuda_fp16.h>
#include <cstdint>

// Problem constants
#define Ln   128
#define Bn   1024
#define Hd   256
#define Dd   512
#define G3   1536
#define ODEH 128
#define INU  32
#define OUTd 16
#define ROWS (Ln * Bn)  // 131072
#define NBLK 128        // persistent grid, 1 CTA/SM via smem

typedef __half fp16;

// ---------------- scratch (device globals; no allocs allowed) ----------------
__device__ fp16  g_Xh [(size_t)ROWS * Dd];     // embeddings fp16 (m-major)
__device__ float g_giT[(size_t)Ln * G3 * Bn];  // gi TRANSPOSED [t][gate*512+d][b]
__device__ float g_hnT[(size_t)Ln * Dd * Bn];  // hn history TRANSPOSED [t][d][b]
__device__ float g_tmpT[(size_t)Dd * Bn];      // GRU out TRANSPOSED [d][b]
__device__ fp16  g_hh [Bn * Dd];               // current h fp16 (m-major)
__device__ fp16  g_Wih[G3 * Dd];               // W_ih fp16
__device__ fp16  g_Whh[G3 * Dd];               // W_hh fp16
__device__ unsigned g_barG[16 * 32];           // per-mg group barrier counters (128B apart)

// ---------------- smem map ----------------
// W: 3 regions (one per gate), each 64 rows x 512 k fp16, 1024B/row,
//    16B-slot XOR swizzle (slot ^ (n&7)) -> conflict-free ldmatrix.
#define W_REGION 65536
#define SW_BYTES (3 * W_REGION)           // 196608
#define OFF_SA   SW_BYTES
// A double buffer: 2 x 8192 (NS=1)
#define SMEM_TOTAL (SW_BYTES + 32768)     // 229376 (ODE overlay also lives here)

// ---------------- asm helpers ----------------
__device__ __forceinline__ uint32_t smem_to_u32(const void* p) {
    uint32_t a;
    asm("{ .reg .u64 t; cvta.to.shared.u64 t, %1; cvt.u32.u64 %0, t; }" : "=r"(a) : "l"(p));
    return a;
}
__device__ __forceinline__ void mma16816(float* c, const unsigned* a, const unsigned* b) {
    asm volatile(
        "mma.sync.aligned.m16n8k16.row.col.f32.f16.f16.f32 "
        "{%0,%1,%2,%3}, {%4,%5,%6,%7}, {%8,%9}, {%0,%1,%2,%3};\n"
        : "+f"(c[0]), "+f"(c[1]), "+f"(c[2]), "+f"(c[3])
        : "r"(a[0]), "r"(a[1]), "r"(a[2]), "r"(a[3]), "r"(b[0]), "r"(b[1]));
}
__device__ __forceinline__ void ldsm4(uint32_t addr, uint32_t* r) {
    asm volatile("ldmatrix.sync.aligned.m8n8.x4.shared.b16 {%0,%1,%2,%3}, [%4];"
                 : "=r"(r[0]), "=r"(r[1]), "=r"(r[2]), "=r"(r[3]) : "r"(addr));
}
#define CP16(dst, src) asm volatile("cp.async.cg.shared.global [%0], [%1], 16;" :: "r"(dst), "l"(src))
#define CPCOMMIT()     asm volatile("cp.async.commit_group;" ::: "memory")
#define CPWAIT0()      asm volatile("cp.async.wait_group 0;" ::: "memory")

// ---------------- init ----------------
__global__ void k_zero() {
    int i = blockIdx.x * 1024 + threadIdx.x;   // 512x1024 = Bn*Dd
    g_hnT[i] = 0.0f;
    g_hh[i] = __float2half(0.0f);
    if (i < 16 * 32) g_barG[i] = 0u;
}

__global__ void k_wconv(const float* __restrict__ W, fp16* __restrict__ Wo) {
    size_t i = (size_t)blockIdx.x * 512 + threadIdx.x;
    Wo[i] = __float2half(W[i]);
}

// ---------------- embeddings: 1024 blocks x 128 rows, weights staged once ----------------
__global__ __launch_bounds__(256) void k_embed(
    const float* __restrict__ ext, const float* __restrict__ obs,
    const float* __restrict__ Wu, const float* __restrict__ bu,
    const float* __restrict__ Wx, const float* __restrict__ bx)
{
    __shared__ float sWu[INU * Hd];    // 32 KB  (k-major: sWu[k*256+col])
    __shared__ float sWx[OUTd * Hd];   // 16 KB
    __shared__ float sIn[128 * INU];   // 16 KB
    __shared__ float sOb[128 * OUTd];  //  8 KB
    const int row0 = blockIdx.x * 128;
    const int tid = threadIdx.x;
    #pragma unroll 4
    for (int i = tid; i < INU * Hd; i += 256) sWu[i] = Wu[i];
    #pragma unroll 4
    for (int i = tid; i < OUTd * Hd; i += 256) sWx[i] = Wx[i];
    #pragma unroll 4
    for (int i = tid; i < 128 * INU; i += 256) {
        int r = i >> 5, k = i & 31;
        sIn[i] = ext[(size_t)(row0 + r) * (INU + 1) + k];
    }
    #pragma unroll 4
    for (int i = tid; i < 128 * OUTd; i += 256) {
        int r = i >> 4, k = i & 15;
        sOb[i] = obs[(size_t)(row0 + r) * OUTd + k];
    }
    __syncthreads();
    const float bu_t = bu[tid];
    const float bx_t = bx[tid];
    for (int r = 0; r < 128; r++) {
        float au = bu_t;
        #pragma unroll
        for (int k = 0; k < INU; k++) au += sIn[r * INU + k] * sWu[k * Hd + tid];
        float ax = bx_t;
        #pragma unroll
        for (int k = 0; k < OUTd; k++) ax += sOb[r * OUTd + k] * sWx[k * Hd + tid];
        size_t base = (size_t)(row0 + r) * Dd;
        g_Xh[base + tid]      = __float2half(tanhf(au));
        g_Xh[base + Hd + tid] = __float2half(tanhf(ax));
    }
}

// ---------------- group barrier (8 blocks sharing mg) ----------------
__device__ __forceinline__ void gbarg(unsigned* ctr, unsigned target) {
    __syncthreads();
    if (threadIdx.x == 0) {
        __threadfence();
        atomicAdd(ctr, 1u);
        while (*((volatile unsigned*)ctr) < target) { }
        __threadfence();
    }
    __syncthreads();
}

// ---------------- W loader: 3 regions, 64 rows, 1024B/row, 16B-slot XOR swizzle ----------------
__device__ void load_Wsw(const fp16* __restrict__ W, int d0, char* sW, int tid) {
    #pragma unroll 4
    for (int it = 0; it < 48; it++) {
        int flat = tid + it * 256;            // uint4 index, 0..12287
        int g = flat >> 12;                   // region 0..2 (gate)
        int rem = flat & 4095;
        int n    = rem >> 6;                  // row 0..63
        int slot = rem & 63;                  // 16B slot (8 fp16)
        uint4 v = *(const uint4*)(W + (size_t)(g * Dd + d0 + n) * Dd + slot * 8);
        *(uint4*)(sW + g * W_REGION + n * 1024 + ((slot ^ (n & 7)) << 4)) = v;
    }
}

// ---------------- GEMM: C[64m x 192n] = A[64,512] @ Wslice^T (single fp16 term) ----------------
// 64k chunks (two 32k sub-chunks), double buffered.
__device__ __forceinline__ void gemm_tile(
    const fp16* __restrict__ Ah,
    uint32_t sAu, float acc[3][2][2][4], int tid,
    uint32_t aBase, uint32_t aSlotL, uint32_t aSw,
    uint32_t bBase, uint32_t bKh, uint32_t bSw)
{
    const uint32_t BUFSZ = 8192u;
    #pragma unroll
    for (int g = 0; g < 3; g++)
        #pragma unroll
        for (int i2 = 0; i2 < 2; i2++)
            #pragma unroll
            for (int j2 = 0; j2 < 2; j2++)
                #pragma unroll
                for (int e = 0; e < 4; e++) acc[g][i2][j2][e] = 0.0f;

    // per-thread fill slots (2 x 16B per buffer); layout: [sub(2)][m(64)][slot(4) swizzled]
    uint32_t fd[2]; const fp16* fs[2];
    #pragma unroll
    for (int i = 0; i < 2; i++) {
        int flat = tid + i * 256;                 // 0..511
        int slot = flat & 3;
        int m = (flat >> 2) & 63;
        int sub = flat >> 8;
        fd[i] = sAu + (uint32_t)sub * 4096u + (uint32_t)m * 64u
                + ((uint32_t)(slot ^ ((m >> 1) & 3)) << 4);
        fs[i] = Ah + (size_t)m * Dd + sub * 32 + slot * 8;
    }
    #pragma unroll
    for (int i = 0; i < 2; i++) CP16(fd[i], fs[i]);
    CPCOMMIT();

    for (int c = 0; c < 8; c++) {                 // 8 chunks x 64 k
        CPWAIT0();
        __syncthreads();
        if (c < 7) {
            uint32_t nb = ((uint32_t)(c + 1) & 1u) * BUFSZ;
            #pragma unroll
            for (int i = 0; i < 2; i++) CP16(fd[i] + nb, fs[i] + (c + 1) * 64);
            CPCOMMIT();
        }
        uint32_t ab = aBase + ((uint32_t)(c & 1)) * BUFSZ;
        #pragma unroll
        for (int sub = 0; sub < 2; sub++) {
            uint32_t absub = ab + (uint32_t)sub * 4096u;
            #pragma unroll
            for (int ks8 = 0; ks8 <= 2; ks8 += 2) {
                uint32_t afr[2][4];
                #pragma unroll
                for (int i2 = 0; i2 < 2; i2++)
                    ldsm4(absub + i2 * 1024u + (((aSlotL + ks8) ^ aSw) << 4), afr[i2]);
                uint32_t bfr[3][4];
                uint32_t bslot = (uint32_t)(c * 8 + sub * 4 + ks8) + bKh;
                #pragma unroll
                for (int g = 0; g < 3; g++)
                    ldsm4(bBase + g * W_REGION + ((bslot ^ bSw) << 4), bfr[g]);
                #pragma unroll
                for (int g = 0; g < 3; g++)
                    #pragma unroll
                    for (int i2 = 0; i2 < 2; i2++)
                        #pragma unroll
                        for (int j2 = 0; j2 < 2; j2++)
                            mma16816(acc[g][i2][j2], afr[i2], &bfr[g][j2 * 2]);
            }
        }
    }
}

// ---------------- THE persistent kernel ----------------
__global__ void __launch_bounds__(256, 1) k_persist(
    const float* __restrict__ ext,
    const float* __restrict__ bih, const float* __restrict__ bhh,
    const float* __restrict__ W1, const float* __restrict__ b1,
    const float* __restrict__ W2, const float* __restrict__ b2)
{
    extern __shared__ char smem[];
    uint32_t sWu_ = smem_to_u32(smem);
    uint32_t sAu = sWu_ + OFF_SA;
    float* s_h  = (float*)(smem + OFF_SA);            // [8][260]   (overlay on sA)
    float* s_zp = (float*)(smem + OFF_SA + 8320);     // [2][8][132] partials -> z in [0]
    float* s_c  = (float*)(smem + OFF_SA + 16768);    // [8][130]
    float* s_dt = (float*)(smem + OFF_SA + 20928);    // [8]

    const int tid = threadIdx.x;
    const int wid = tid >> 5, lane = tid & 31;
    const int bid = blockIdx.x;
    const int dtile = bid & 7, mg = bid >> 3;         // 8 d-tiles x 64, 16 m-groups x 64
    const int d0 = dtile * 64;
    const int m0ode = bid * 8;
    const int warp_m = wid >> 2, warp_n = wid & 3;    // 2 x 4 warp grid
    const int q = lane >> 2, tp = lane & 3;
    unsigned* gctr = &g_barG[mg * 32];
    unsigned bar_t = 0;

    // ldmatrix per-lane constants
    const int aRow = warp_m * 32 + (lane & 7) + ((lane >> 3) & 1) * 8;
    const uint32_t aBase = sAu + (uint32_t)aRow * 64;
    const uint32_t aSlotL = (uint32_t)(lane >> 4);
    const uint32_t aSw = (uint32_t)((aRow >> 1) & 3);
    const int bRowN = warp_n * 16 + (lane & 7) + ((lane >> 4) & 1) * 8;
    const uint32_t bBase = sWu_ + (uint32_t)bRowN * 1024;
    const uint32_t bKh = (uint32_t)((lane >> 3) & 1);
    const uint32_t bSw = (uint32_t)(bRowN & 7);

    float acc[3][2][2][4];

    // per-thread bias values (d depends only on j2, eo)
    float bI[3][2][2], bH[3][2][2];
    #pragma unroll
    for (int g = 0; g < 3; g++)
        #pragma unroll
        for (int j2 = 0; j2 < 2; j2++)
            #pragma unroll
            for (int eo = 0; eo < 2; eo++) {
                int d = d0 + warp_n * 16 + j2 * 8 + tp * 2 + eo;
                bI[g][j2][eo] = bih[g * Dd + d];
                bH[g][j2][eo] = bhh[g * Dd + d];
            }

    // ======== Phase 1: gi = X @ W_ih^T + b_ih ========
    load_Wsw(g_Wih, d0, smem, tid);
    __syncthreads();
    for (int t = 0; t < 127; t++) {
        const fp16* Ah = g_Xh + ((size_t)t * Bn + mg * 64) * Dd;
        gemm_tile(Ah, sAu, acc, tid, aBase, aSlotL, aSw, bBase, bKh, bSw);
        float* giT = g_giT + (size_t)t * G3 * Bn;
        #pragma unroll
        for (int i2 = 0; i2 < 2; i2++)
            #pragma unroll
            for (int j2 = 0; j2 < 2; j2++)
                #pragma unroll
                for (int e = 0; e < 4; e++) {
                    int b = mg * 64 + warp_m * 32 + i2 * 16 + q + (e >> 1) * 8;
                    int d = d0 + warp_n * 16 + j2 * 8 + tp * 2 + (e & 1);
                    #pragma unroll
                    for (int g = 0; g < 3; g++)
                        giT[(size_t)(g * Dd + d) * Bn + b] = acc[g][i2][j2][e] + bI[g][j2][e & 1];
                }
    }

    // ======== Phase 2: recurrent loop (group-local synchronization only) ========
    __syncthreads();                      // all warps done reading W_ih smem
    load_Wsw(g_Whh, d0, smem, tid);
    __syncthreads();

    for (int t = 0; t < 127; t++) {
        gemm_tile(g_hh + (size_t)mg * 64 * Dd, sAu, acc, tid, aBase, aSlotL, aSw, bBase, bKh, bSw);
        // fused GRU gates epilogue -> g_tmpT
        const float* giT = g_giT + (size_t)t * G3 * Bn;
        const float* hpT = g_hnT + (size_t)t * Dd * Bn;
        #pragma unroll
        for (int i2 = 0; i2 < 2; i2++)
            #pragma unroll
            for (int j2 = 0; j2 < 2; j2++)
                #pragma unroll
                for (int e = 0; e < 4; e++) {
                    int b = mg * 64 + warp_m * 32 + i2 * 16 + q + (e >> 1) * 8;
                    int d = d0 + warp_n * 16 + j2 * 8 + tp * 2 + (e & 1);
                    float gR = acc[0][i2][j2][e] + bH[0][j2][e & 1];
                    float gZ = acc[1][i2][j2][e] + bH[1][j2][e & 1];
                    float gN = acc[2][i2][j2][e] + bH[2][j2][e & 1];
                    float giR = __ldcg(&giT[(size_t)d * Bn + b]);
                    float giZ = __ldcg(&giT[(size_t)(Dd + d) * Bn + b]);
                    float giN = __ldcg(&giT[(size_t)(2 * Dd + d) * Bn + b]);
                    float r = 1.0f / (1.0f + __expf(-(giR + gR)));
                    float z = 1.0f / (1.0f + __expf(-(giZ + gZ)));
                    float nn = tanhf(giN + r * gN);
                    float hp = __ldcg(&hpT[(size_t)d * Bn + b]);
                    g_tmpT[(size_t)d * Bn + b] = (1.0f - z) * nn + z * hp;
                }
        bar_t += 8; gbarg(gctr, bar_t);   // group's epilogues done

        // ---- ODE MLP + Euler for rows m0ode..m0ode+7 ----
        #pragma unroll
        for (int i = 0; i < 8; i++) {
            int idx = tid + i * 256;
            int r = idx & 7, cc = idx >> 3;           // cc 0..255
            s_h[r * 260 + cc] = __ldcg(&g_tmpT[(size_t)cc * Bn + m0ode + r]);
        }
        if (tid < 8) s_dt[tid] = ext[((size_t)t * Bn + m0ode + tid) * (INU + 1) + INU];
        __syncthreads();
        {   // z = tanh(h @ W1 + b1), k-split across warp halves (W1 read exactly once)
            int col = tid & 127, half = tid >> 7;
            float a[8];
            #pragma unroll
            for (int r = 0; r < 8; r++) a[r] = 0.0f;
            const int kb = half * 128;
            #pragma unroll 4
            for (int k = 0; k < 128; k++) {
                float w = W1[(kb + k) * ODEH + col];
                #pragma unroll
                for (int r = 0; r < 8; r++) a[r] += s_h[r * 260 + kb + k] * w;
            }
            #pragma unroll
            for (int r = 0; r < 8; r++) s_zp[half * 1056 + r * 132 + col] = a[r];
        }
        __syncthreads();
        #pragma unroll
        for (int i = 0; i < 4; i++) {                 // combine halves + tanh (into s_zp[0])
            int idx = tid + i * 256;
            int r = idx >> 7, c = idx & 127;
            s_zp[r * 132 + c] = tanhf(s_zp[r * 132 + c] + s_zp[1056 + r * 132 + c] + b1[c]);
        }
        __syncthreads();
        float hnew[8];
        {   // f = z @ W2 + b2 ; hnew = h + dt*f ; write g_hh (h part, m-major)
            int col = tid;
            float f[8];
            float bb = b2[col];
            #pragma unroll
            for (int r = 0; r < 8; r++) f[r] = bb;
            #pragma unroll 4
            for (int k = 0; k < ODEH; k++) {
                float w = W2[k * Hd + col];
                #pragma unroll
                for (int r = 0; r < 8; r++) f[r] += s_zp[r * 132 + k] * w;
            }
            #pragma unroll
            for (int r = 0; r < 8; r++) {
                hnew[r] = s_h[r * 260 + col] + s_dt[r] * f[r];
                g_hh[(size_t)(m0ode + r) * Dd + col] = __float2half(hnew[r]);
                s_h[r * 260 + col] = hnew[r];         // same-thread same-address: no sync needed
            }
        }
        __syncthreads();
        float* hnT1 = g_hnT + (size_t)(t + 1) * Dd * Bn;
        #pragma unroll
        for (int i = 0; i < 8; i++) {
            int idx = tid + i * 256;
            int r = idx & 7, cc = idx >> 3;
            hnT1[(size_t)cc * Bn + m0ode + r] = s_h[r * 260 + cc];
        }
        #pragma unroll
        for (int ch = 0; ch < 2; ch++) {              // c passthrough (to hnT1 + g_hh fp16)
            int cbase = Hd + ch * 128;
            #pragma unroll
            for (int i = 0; i < 4; i++) {
                int idx = tid + i * 256;
                int r = idx & 7, cl = idx >> 3;
                float x = __ldcg(&g_tmpT[(size_t)(cbase + cl) * Bn + m0ode + r]);
                hnT1[(size_t)(cbase + cl) * Bn + m0ode + r] = x;
                s_c[r * 130 + cl] = x;
            }
            __syncthreads();
            #pragma unroll
            for (int i = 0; i < 4; i++) {
                int idx = tid + i * 256;
                int r = idx >> 7, cl = idx & 127;
                g_hh[(size_t)(m0ode + r) * Dd + cbase + cl] = __float2half(s_c[r * 130 + cl]);
            }
            __syncthreads();
        }
        bar_t += 8; gbarg(gctr, bar_t);   // group's ODE done -> next GEMM may read g_hh
    }
}

// ---------------- output projection ----------------
__global__ __launch_bounds__(256) void k_out(
    const float* __restrict__ WLy, const float* __restrict__ bLy,
    float* __restrict__ out)
{
    __shared__ float s_w[Dd * OUTd];   // 32 KB
    int t = blockIdx.x >> 3;
    int b0 = (blockIdx.x & 7) * 128;
    int tid = threadIdx.x;
    #pragma unroll
    for (int i = 0; i < 32; i++) s_w[tid + i * 256] = WLy[tid + i * 256];
    __syncthreads();
    int b = b0 + (tid >> 1);
    int oh = (tid & 1) * 8;
    const float* hp = g_hnT + (size_t)t * Dd * Bn;
    float a[8];
    #pragma unroll
    for (int j = 0; j < 8; j++) a[j] = bLy[oh + j];
    #pragma unroll 4
    for (int k = 0; k < Dd; k++) {
        float v = __ldg(&hp[(size_t)k * Bn + b]);
        #pragma unroll
        for (int j = 0; j < 8; j++) a[j] += v * s_w[k * OUTd + oh + j];
    }
    float* op = out + ((size_t)t * Bn + b) * OUTd + oh;
    *(float4*)(op)     = make_float4(a[0], a[1], a[2], a[3]);
    *(float4*)(op + 4) = make_float4(a[4], a[5], a[6], a[7]);
}

// ---------------- launch ----------------
extern "C" void kernel_launch(void* const* d_in, const int* in_sizes, int n_in,
                              void* d_out, int out_size)
{
    const float* ext = (const float*)d_in[0];
    const float* obs = (const float*)d_in[1];
    const float* Wu  = (const float*)d_in[2];
    const float* bu  = (const float*)d_in[3];
    const float* Wx  = (const float*)d_in[4];
    const float* bx  = (const float*)d_in[5];
    const float* Wih = (const float*)d_in[6];
    const float* Whh = (const float*)d_in[7];
    const float* bih = (const float*)d_in[8];
    const float* bhh = (const float*)d_in[9];
    const float* W1  = (const float*)d_in[10];
    const float* b1  = (const float*)d_in[11];
    const float* W2  = (const float*)d_in[12];
    const float* b2  = (const float*)d_in[13];
    const float* WLy = (const float*)d_in[14];
    const float* bLy = (const float*)d_in[15];
    float* out = (float*)d_out;

    fp16 *p_Wih, *p_Whh;
    cudaGetSymbolAddress((void**)&p_Wih, g_Wih);
    cudaGetSymbolAddress((void**)&p_Whh, g_Whh);

    cudaFuncSetAttribute(k_persist, cudaFuncAttributeMaxDynamicSharedMemorySize, SMEM_TOTAL);

    k_zero<<<512, 1024>>>();
    k_wconv<<<G3, 512>>>(Wih, p_Wih);
    k_wconv<<<G3, 512>>>(Whh, p_Whh);
    k_embed<<<ROWS / 128, 256>>>(ext, obs, Wu, bu, Wx, bx);

    k_persist<<<NBLK, 256, SMEM_TOTAL>>>(ext, bih, bhh, W1, b1, W2, b2);

    k_out<<<Ln * 8, 256>>>(WLy, bLy, out);
}